// round 7
// baseline (speedup 1.0000x reference)
#include <cuda_runtime.h>
#include <cuda_bf16.h>
#include <cstdint>

// Problem constants
#define B_WIN 256
#define NTOK  144
#define DIM   384
#define HEADS 12
#define HD    32
#define QKV_N 1152
#define MROWS (B_WIN*NTOK)        // 36864
#define QSCALE 0.17677669529663689f   // 32^-0.5
#define QKV_PLANE 56623104ll          // 3072*144*128 bytes per q/k/v plane

// ---------------- Scratch (static device globals; allocation-free) ----------
__device__ char g_qkvp[169869312];            // packed q/k/v (see R6 layout)
__device__ __nv_bfloat16 g_xa_hi[14155776];   // x split, [36864][384]
__device__ __nv_bfloat16 g_xa_lo[14155776];
__device__ __nv_bfloat16 g_wqkvT_hi[442368];  // [1152][384]
__device__ __nv_bfloat16 g_wqkvT_lo[442368];
__device__ __nv_bfloat16 g_woutT_hi[147456];  // [384][384]
__device__ __nv_bfloat16 g_woutT_lo[147456];
__device__ __nv_bfloat16 g_att_hi[14155776];  // attention out split, [36864][384]
__device__ __nv_bfloat16 g_att_lo[14155776];

// ---------------- helpers ---------------------------------------------------
__device__ __forceinline__ uint32_t smem_u32(const void* p) {
    return (uint32_t)__cvta_generic_to_shared(p);
}
__device__ __forceinline__ uint32_t pack_bf2(__nv_bfloat16 a, __nv_bfloat16 b) {
    return (uint32_t)__bfloat16_as_ushort(a) | ((uint32_t)__bfloat16_as_ushort(b) << 16);
}
__device__ __forceinline__ void ldsm_x4(uint32_t* r, uint32_t addr) {
    asm volatile("ldmatrix.sync.aligned.m8n8.x4.shared.b16 {%0,%1,%2,%3}, [%4];"
                 : "=r"(r[0]), "=r"(r[1]), "=r"(r[2]), "=r"(r[3]) : "r"(addr));
}
__device__ __forceinline__ void ldsm_x4_t(uint32_t* r, uint32_t addr) {
    asm volatile("ldmatrix.sync.aligned.m8n8.x4.trans.shared.b16 {%0,%1,%2,%3}, [%4];"
                 : "=r"(r[0]), "=r"(r[1]), "=r"(r[2]), "=r"(r[3]) : "r"(addr));
}
__device__ __forceinline__ void mma_bf16(float* c, const uint32_t* a, const uint32_t* b) {
    asm volatile(
        "mma.sync.aligned.m16n8k16.row.col.f32.bf16.bf16.f32 "
        "{%0,%1,%2,%3}, {%4,%5,%6,%7}, {%8,%9}, {%0,%1,%2,%3};"
        : "+f"(c[0]), "+f"(c[1]), "+f"(c[2]), "+f"(c[3])
        : "r"(a[0]), "r"(a[1]), "r"(a[2]), "r"(a[3]), "r"(b[0]), "r"(b[1]));
}
__device__ __forceinline__ void cp_async16(uint32_t s, const void* g) {
    asm volatile("cp.async.cg.shared.global [%0], [%1], 16;" :: "r"(s), "l"(g));
}
#define CP_COMMIT() asm volatile("cp.async.commit_group;" ::: "memory")
#define CP_WAIT1()  asm volatile("cp.async.wait_group 1;" ::: "memory")
#define CP_WAIT0()  asm volatile("cp.async.wait_group 0;" ::: "memory")

// ---------------------------------------------------------------------------
// Prep: split x (fp32) into bf16 hi/lo
// ---------------------------------------------------------------------------
__global__ void convert_x_kernel(const float* __restrict__ x,
                                 __nv_bfloat16* __restrict__ hi,
                                 __nv_bfloat16* __restrict__ lo, int n4)
{
    int idx = blockIdx.x * blockDim.x + threadIdx.x;
    int stride = gridDim.x * blockDim.x;
    for (; idx < n4; idx += stride) {
        float4 v = ((const float4*)x)[idx];
        __nv_bfloat16 h0 = __float2bfloat16(v.x);
        __nv_bfloat16 h1 = __float2bfloat16(v.y);
        __nv_bfloat16 h2 = __float2bfloat16(v.z);
        __nv_bfloat16 h3 = __float2bfloat16(v.w);
        __nv_bfloat16 l0 = __float2bfloat16(v.x - __bfloat162float(h0));
        __nv_bfloat16 l1 = __float2bfloat16(v.y - __bfloat162float(h1));
        __nv_bfloat16 l2 = __float2bfloat16(v.z - __bfloat162float(h2));
        __nv_bfloat16 l3 = __float2bfloat16(v.w - __bfloat162float(h3));
        ((uint2*)hi)[idx] = make_uint2(pack_bf2(h0, h1), pack_bf2(h2, h3));
        ((uint2*)lo)[idx] = make_uint2(pack_bf2(l0, l1), pack_bf2(l2, l3));
    }
}

// Prep: transpose + split weight w[K][Nn] -> wT[Nn][K] bf16 hi/lo
__global__ void convert_wT_kernel(const float* __restrict__ w,
                                  __nv_bfloat16* __restrict__ hi,
                                  __nv_bfloat16* __restrict__ lo,
                                  int K, int Nn)
{
    int idx = blockIdx.x * blockDim.x + threadIdx.x;
    int total = K * Nn;
    if (idx >= total) return;
    int n = idx / K, k = idx - n * K;
    float v = w[(size_t)k * Nn + n];
    __nv_bfloat16 h = __float2bfloat16(v);
    __nv_bfloat16 l = __float2bfloat16(v - __bfloat162float(h));
    hi[idx] = h;
    lo[idx] = l;
}

// ---------------------------------------------------------------------------
// HMMA split-bf16 GEMM with 2-stage cp.async pipeline.
// D(128x128) = A(128x384) @ B^T(128x384), fp32 accum, BK=64.
// smem: 2 stages x 4 tiles x 16KB = 128KB.
// mode 0: qkv epilogue -> packed bf16 hi/lo q/k/v planes (+bias, q-scale)
// mode 1: out epilogue (bias, write fp32 out)
// ---------------------------------------------------------------------------
#define TILE_B 16384
#define STAGE_B (4 * TILE_B)

__global__ __launch_bounds__(256, 1)
void hmma_gemm_kernel(const __nv_bfloat16* __restrict__ Ah,
                      const __nv_bfloat16* __restrict__ Al,
                      const __nv_bfloat16* __restrict__ Bh,
                      const __nv_bfloat16* __restrict__ Bl,
                      const float* __restrict__ bias,
                      float* __restrict__ outp, int mode, int kchunks)
{
    extern __shared__ char smem[];
    const uint32_t usm = smem_u32(smem);

    const int tid = threadIdx.x;
    const int wid = tid >> 5, lane = tid & 31;
    const int bm = blockIdx.y * 128;
    const int bn = blockIdx.x * 128;
    const int wm = wid >> 2, wn = wid & 3;
    const int m0w = wm * 64, n0w = wn * 32;

    // per-thread load geometry (one 16B line x 4 iters x 4 tiles)
    const int r4 = tid >> 3;             // 0..31 base row
    const int c4 = tid & 7;              // chunk
    const uint32_t dsw = ((c4 ^ (r4 & 7)) * 16);

    float acc[4][4][4];
#pragma unroll
    for (int mt = 0; mt < 4; mt++)
#pragma unroll
        for (int nt = 0; nt < 4; nt++)
#pragma unroll
            for (int e = 0; e < 4; e++) acc[mt][nt][e] = 0.f;

    const int lr = lane & 15;
    const int lc = lane >> 4;

    // ---- stage fill helper (as lambda-ish macro over kc, buf) ----
#define LOAD_STAGE(kc, buf)                                                     \
    {                                                                           \
        uint32_t s0 = usm + (buf) * STAGE_B;                                    \
        _Pragma("unroll")                                                       \
        for (int it = 0; it < 4; it++) {                                        \
            int r = r4 + it * 32;                                               \
            size_t gA = (size_t)(bm + r) * 384 + (kc) * 64 + c4 * 8;            \
            size_t gB = (size_t)(bn + r) * 384 + (kc) * 64 + c4 * 8;            \
            uint32_t d = r * 128 + ((c4 ^ (r & 7)) * 16);                       \
            cp_async16(s0 + d, Ah + gA);                                        \
            cp_async16(s0 + TILE_B + d, Al + gA);                               \
            cp_async16(s0 + 2 * TILE_B + d, Bh + gB);                           \
            cp_async16(s0 + 3 * TILE_B + d, Bl + gB);                           \
        }                                                                       \
        CP_COMMIT();                                                            \
    }

    LOAD_STAGE(0, 0);

    for (int kc = 0; kc < kchunks; kc++) {
        if (kc + 1 < kchunks) {
            LOAD_STAGE(kc + 1, (kc + 1) & 1);
            CP_WAIT1();
        } else {
            CP_WAIT0();
        }
        __syncthreads();

        const uint32_t uAh = usm + (kc & 1) * STAGE_B;
        const uint32_t uAl = uAh + TILE_B;
        const uint32_t uBh = uAh + 2 * TILE_B;
        const uint32_t uBl = uAh + 3 * TILE_B;

#pragma unroll
        for (int k16 = 0; k16 < 4; k16++) {
            const int chunk = k16 * 2 + lc;
            uint32_t aH[4][4], aL[4][4];
            uint32_t bH[4][2], bL[4][2];
#pragma unroll
            for (int mt = 0; mt < 4; mt++) {
                int r = m0w + mt * 16 + lr;
                uint32_t off = r * 128 + ((chunk ^ (r & 7)) * 16);
                ldsm_x4(aH[mt], uAh + off);
                ldsm_x4(aL[mt], uAl + off);
            }
#pragma unroll
            for (int np = 0; np < 2; np++) {
                int r = n0w + np * 16 + lr;
                uint32_t off = r * 128 + ((chunk ^ (r & 7)) * 16);
                uint32_t t[4];
                ldsm_x4(t, uBh + off);
                bH[2 * np][0] = t[0]; bH[2 * np][1] = t[2];
                bH[2 * np + 1][0] = t[1]; bH[2 * np + 1][1] = t[3];
                ldsm_x4(t, uBl + off);
                bL[2 * np][0] = t[0]; bL[2 * np][1] = t[2];
                bL[2 * np + 1][0] = t[1]; bL[2 * np + 1][1] = t[3];
            }
#pragma unroll
            for (int mt = 0; mt < 4; mt++)
#pragma unroll
                for (int nt = 0; nt < 4; nt++) {
                    mma_bf16(acc[mt][nt], aH[mt], bH[nt]);
                    mma_bf16(acc[mt][nt], aH[mt], bL[nt]);
                    mma_bf16(acc[mt][nt], aL[mt], bH[nt]);
                }
        }
        __syncthreads();
    }
#undef LOAD_STAGE

    if (mode == 0) {
        // write packed bf16 hi/lo q/k/v planes
#pragma unroll
        for (int mt = 0; mt < 4; mt++) {
#pragma unroll
            for (int nt = 0; nt < 4; nt++) {
                int col = bn + n0w + nt * 8 + (lane & 3) * 2;
                int s = col / 384;
                int rem = col - s * 384;
                int hh = rem >> 5, d = rem & 31;
                float sc = (s == 0) ? QSCALE : 1.0f;
                float b0 = bias[col], b1 = bias[col + 1];
                char* plane = g_qkvp + (size_t)s * QKV_PLANE;
                int lH = d >> 3, lL = 4 + (d >> 3);
                int byt = (d & 7) * 2;
#pragma unroll
                for (int half = 0; half < 2; half++) {
                    int row = bm + m0w + mt * 16 + (lane >> 2) + half * 8;
                    int b = row / 144, i = row - b * 144;
                    float v0 = (acc[mt][nt][half * 2 + 0] + b0) * sc;
                    float v1 = (acc[mt][nt][half * 2 + 1] + b1) * sc;
                    __nv_bfloat16 h0 = __float2bfloat16(v0);
                    __nv_bfloat16 h1 = __float2bfloat16(v1);
                    uint32_t hiW = pack_bf2(h0, h1);
                    uint32_t loW = pack_bf2(__float2bfloat16(v0 - __bfloat162float(h0)),
                                            __float2bfloat16(v1 - __bfloat162float(h1)));
                    char* base = plane + ((size_t)(b * 12 + hh) * 144 + i) * 128;
                    *(uint32_t*)(base + ((lH ^ (i & 7)) * 16) + byt) = hiW;
                    *(uint32_t*)(base + ((lL ^ (i & 7)) * 16) + byt) = loW;
                }
            }
        }
    } else {
#pragma unroll
        for (int mt = 0; mt < 4; mt++) {
#pragma unroll
            for (int nt = 0; nt < 4; nt++) {
                int col = bn + n0w + nt * 8 + (lane & 3) * 2;
                float b0 = bias[col], b1 = bias[col + 1];
#pragma unroll
                for (int half = 0; half < 2; half++) {
                    int row = bm + m0w + mt * 16 + (lane >> 2) + half * 8;
                    float2 v;
                    v.x = acc[mt][nt][half * 2 + 0] + b0;
                    v.y = acc[mt][nt][half * 2 + 1] + b1;
                    *(float2*)(outp + (size_t)row * 384 + col) = v;
                }
            }
        }
    }
}

// ---------------------------------------------------------------------------
// Flash-style HMMA attention (unchanged from R6)
// ---------------------------------------------------------------------------
__global__ __launch_bounds__(288, 1)
void attn_mma_kernel(const float* __restrict__ mask,
                     const float* __restrict__ bias_table,
                     const int*   __restrict__ pos_idx)
{
    extern __shared__ char sm[];
    char* sQ = sm;
    char* sK = sm + 18432;
    char* sV = sm + 36864;
    float* sB = (float*)(sm + 55296);
    const uint32_t uQ = smem_u32(sQ), uK = smem_u32(sK), uV = smem_u32(sV);

    const int bh = blockIdx.x;
    const int b = bh / HEADS, h = bh - b * HEADS;
    const int g  = b >> 5;
    const int t  = b & 31;
    const int mw = b & 7;

    const int tid = threadIdx.x;
    const int wid = tid >> 5, lane = tid & 31;

    {
        const uint4* q = (const uint4*)(g_qkvp + (size_t)bh * 18432);
        const uint4* k = (const uint4*)(g_qkvp + QKV_PLANE + (size_t)bh * 18432);
        const uint4* v = (const uint4*)(g_qkvp + 2 * QKV_PLANE + (size_t)bh * 18432);
        uint4* dq = (uint4*)sQ; uint4* dk = (uint4*)sK; uint4* dv = (uint4*)sV;
        for (int i = tid; i < 1152; i += 288) { dq[i] = q[i]; dk[i] = k[i]; dv[i] = v[i]; }
    }
    for (int s = tid; s < 2592; s += 288)
        sB[s] = bias_table[(size_t)pos_idx[8 * s + g] * (32 * HEADS) + t * HEADS + h];
    __syncthreads();

    const int m0 = wid * 16;
    const int gr = lane >> 2, q2 = lane & 3;
    const int i0 = m0 + gr, i1 = i0 + 8;

    float c[18][4];
    {
        const float* mrow0 = mask + ((size_t)mw * 144 + i0) * 144;
        const float* mrow1 = mask + ((size_t)mw * 144 + i1) * 144;
        const float* brow0 = sB + (i0 % 18) * 144;
        const float* brow1 = sB + (i1 % 18) * 144;
#pragma unroll
        for (int nt = 0; nt < 18; nt++) {
            int j = nt * 8 + q2 * 2;
            float2 mv0 = *(const float2*)(mrow0 + j);
            float2 mv1 = *(const float2*)(mrow1 + j);
            float2 bv0 = *(const float2*)(brow0 + j);
            float2 bv1 = *(const float2*)(brow1 + j);
            c[nt][0] = mv0.x + bv0.x; c[nt][1] = mv0.y + bv0.y;
            c[nt][2] = mv1.x + bv1.x; c[nt][3] = mv1.y + bv1.y;
        }
    }

    const int lr = lane & 15, lc = lane >> 4;
#pragma unroll
    for (int kk = 0; kk < 2; kk++) {
        uint32_t aH[4], aL[4];
        {
            int r = m0 + lr;
            int lH = kk * 2 + lc, lL = lH + 4;
            ldsm_x4(aH, uQ + r * 128 + ((lH ^ (r & 7)) * 16));
            ldsm_x4(aL, uQ + r * 128 + ((lL ^ (r & 7)) * 16));
        }
#pragma unroll
        for (int np = 0; np < 9; np++) {
            int r = np * 16 + lr;
            int lH = kk * 2 + lc, lL = lH + 4;
            uint32_t tH[4], tL[4];
            ldsm_x4(tH, uK + r * 128 + ((lH ^ (r & 7)) * 16));
            ldsm_x4(tL, uK + r * 128 + ((lL ^ (r & 7)) * 16));
            uint32_t b0H[2] = {tH[0], tH[2]}, b1H[2] = {tH[1], tH[3]};
            uint32_t b0L[2] = {tL[0], tL[2]}, b1L[2] = {tL[1], tL[3]};
            mma_bf16(c[2 * np],     aH, b0H);
            mma_bf16(c[2 * np],     aH, b0L);
            mma_bf16(c[2 * np],     aL, b0H);
            mma_bf16(c[2 * np + 1], aH, b1H);
            mma_bf16(c[2 * np + 1], aH, b1L);
            mma_bf16(c[2 * np + 1], aL, b1H);
        }
    }

    float mx0 = -1e30f, mx1 = -1e30f;
#pragma unroll
    for (int nt = 0; nt < 18; nt++) {
        mx0 = fmaxf(mx0, fmaxf(c[nt][0], c[nt][1]));
        mx1 = fmaxf(mx1, fmaxf(c[nt][2], c[nt][3]));
    }
    mx0 = fmaxf(mx0, __shfl_xor_sync(0xffffffffu, mx0, 1));
    mx0 = fmaxf(mx0, __shfl_xor_sync(0xffffffffu, mx0, 2));
    mx1 = fmaxf(mx1, __shfl_xor_sync(0xffffffffu, mx1, 1));
    mx1 = fmaxf(mx1, __shfl_xor_sync(0xffffffffu, mx1, 2));
    float s0 = 0.f, s1 = 0.f;
#pragma unroll
    for (int nt = 0; nt < 18; nt++) {
        c[nt][0] = __expf(c[nt][0] - mx0); s0 += c[nt][0];
        c[nt][1] = __expf(c[nt][1] - mx0); s0 += c[nt][1];
        c[nt][2] = __expf(c[nt][2] - mx1); s1 += c[nt][2];
        c[nt][3] = __expf(c[nt][3] - mx1); s1 += c[nt][3];
    }
    s0 += __shfl_xor_sync(0xffffffffu, s0, 1);
    s0 += __shfl_xor_sync(0xffffffffu, s0, 2);
    s1 += __shfl_xor_sync(0xffffffffu, s1, 1);
    s1 += __shfl_xor_sync(0xffffffffu, s1, 2);
    float inv0 = 1.f / s0, inv1 = 1.f / s1;
#pragma unroll
    for (int nt = 0; nt < 18; nt++) {
        c[nt][0] *= inv0; c[nt][1] *= inv0;
        c[nt][2] *= inv1; c[nt][3] *= inv1;
    }

    float o[4][4];
#pragma unroll
    for (int ng = 0; ng < 4; ng++)
#pragma unroll
        for (int e = 0; e < 4; e++) o[ng][e] = 0.f;

    const int grp = lane >> 3, wi = lane & 7;
#pragma unroll
    for (int kk = 0; kk < 9; kk++) {
        uint32_t ah[4], al[4];
#pragma unroll
        for (int p = 0; p < 4; p++) {
            const float x = c[(p < 2) ? 2 * kk : 2 * kk + 1][(p & 1) * 2 + 0];
            const float y = c[(p < 2) ? 2 * kk : 2 * kk + 1][(p & 1) * 2 + 1];
            __nv_bfloat16 hx = __float2bfloat16(x);
            __nv_bfloat16 hy = __float2bfloat16(y);
            ah[p] = pack_bf2(hx, hy);
            al[p] = pack_bf2(__float2bfloat16(x - __bfloat162float(hx)),
                             __float2bfloat16(y - __bfloat162float(hy)));
        }
        int r = kk * 16 + (grp & 1) * 8 + wi;
#pragma unroll
        for (int ncp = 0; ncp < 2; ncp++) {
            int lH = ncp * 2 + (grp >> 1), lL = lH + 4;
            uint32_t th[4], tl[4];
            ldsm_x4_t(th, uV + r * 128 + ((lH ^ (r & 7)) * 16));
            ldsm_x4_t(tl, uV + r * 128 + ((lL ^ (r & 7)) * 16));
            uint32_t bh0[2] = {th[0], th[1]}, bh1[2] = {th[2], th[3]};
            uint32_t bl0[2] = {tl[0], tl[1]}, bl1[2] = {tl[2], tl[3]};
            mma_bf16(o[ncp * 2],     ah, bh0);
            mma_bf16(o[ncp * 2],     ah, bl0);
            mma_bf16(o[ncp * 2],     al, bh0);
            mma_bf16(o[ncp * 2 + 1], ah, bh1);
            mma_bf16(o[ncp * 2 + 1], ah, bl1);
            mma_bf16(o[ncp * 2 + 1], al, bh1);
        }
    }

#pragma unroll
    for (int ng = 0; ng < 4; ng++) {
        int d = ng * 8 + q2 * 2;
        int col = h * 32 + d;
        size_t r0o = ((size_t)b * 144 + i0) * 384 + col;
        size_t r1o = ((size_t)b * 144 + i1) * 384 + col;
        __nv_bfloat16 h0 = __float2bfloat16(o[ng][0]);
        __nv_bfloat16 h1 = __float2bfloat16(o[ng][1]);
        __nv_bfloat16 h2 = __float2bfloat16(o[ng][2]);
        __nv_bfloat16 h3 = __float2bfloat16(o[ng][3]);
        *(uint32_t*)(g_att_hi + r0o) = pack_bf2(h0, h1);
        *(uint32_t*)(g_att_hi + r1o) = pack_bf2(h2, h3);
        *(uint32_t*)(g_att_lo + r0o) =
            pack_bf2(__float2bfloat16(o[ng][0] - __bfloat162float(h0)),
                     __float2bfloat16(o[ng][1] - __bfloat162float(h1)));
        *(uint32_t*)(g_att_lo + r1o) =
            pack_bf2(__float2bfloat16(o[ng][2] - __bfloat162float(h2)),
                     __float2bfloat16(o[ng][3] - __bfloat162float(h3)));
    }
}

// ---------------------------------------------------------------------------
extern "C" void kernel_launch(void* const* d_in, const int* in_sizes, int n_in,
                              void* d_out, int out_size)
{
    const float* x          = (const float*)d_in[0];
    const float* mask       = (const float*)d_in[1];
    const float* w_qkv      = (const float*)d_in[2];
    const float* b_qkv      = (const float*)d_in[3];
    const float* w_out      = (const float*)d_in[4];
    const float* b_out      = (const float*)d_in[5];
    const float* bias_table = (const float*)d_in[6];
    const int*   pos_idx    = (const int*)d_in[7];
    float* out = (float*)d_out;

    __nv_bfloat16 *xa_hi, *xa_lo, *wqT_hi, *wqT_lo, *woT_hi, *woT_lo;
    __nv_bfloat16 *att_hi, *att_lo;
    cudaGetSymbolAddress((void**)&xa_hi, g_xa_hi);
    cudaGetSymbolAddress((void**)&xa_lo, g_xa_lo);
    cudaGetSymbolAddress((void**)&wqT_hi, g_wqkvT_hi);
    cudaGetSymbolAddress((void**)&wqT_lo, g_wqkvT_lo);
    cudaGetSymbolAddress((void**)&woT_hi, g_woutT_hi);
    cudaGetSymbolAddress((void**)&woT_lo, g_woutT_lo);
    cudaGetSymbolAddress((void**)&att_hi, g_att_hi);
    cudaGetSymbolAddress((void**)&att_lo, g_att_lo);

    const int smem_gemm = 2 * STAGE_B;  // 128 KB
    cudaFuncSetAttribute(hmma_gemm_kernel, cudaFuncAttributeMaxDynamicSharedMemorySize,
                         smem_gemm);
    const int smem_attn = 3 * 18432 + 2592 * 4;  // 65664
    cudaFuncSetAttribute(attn_mma_kernel, cudaFuncAttributeMaxDynamicSharedMemorySize,
                         smem_attn);

    convert_x_kernel<<<2048, 256>>>(x, xa_hi, xa_lo, MROWS * DIM / 4);
    convert_wT_kernel<<<(DIM * QKV_N + 255) / 256, 256>>>(w_qkv, wqT_hi, wqT_lo,
                                                          DIM, QKV_N);
    convert_wT_kernel<<<(DIM * DIM + 255) / 256, 256>>>(w_out, woT_hi, woT_lo,
                                                        DIM, DIM);
    // qkv projection -> packed q/k/v
    hmma_gemm_kernel<<<dim3(QKV_N / 128, MROWS / 128), 256, smem_gemm>>>(
        xa_hi, xa_lo, wqT_hi, wqT_lo, b_qkv, nullptr, 0, 6);
    // attention
    attn_mma_kernel<<<B_WIN * HEADS, 288, smem_attn>>>(mask, bias_table, pos_idx);
    // output projection
    hmma_gemm_kernel<<<dim3(DIM / 128, MROWS / 128), 256, smem_gemm>>>(
        att_hi, att_lo, woT_hi, woT_lo, b_out, out, 1, 6);
}

// round 9
// speedup vs baseline: 1.0296x; 1.0296x over previous
#include <cuda_runtime.h>
#include <cuda_bf16.h>
#include <cstdint>

// Problem constants
#define B_WIN 256
#define NTOK  144
#define DIM   384
#define HEADS 12
#define HD    32
#define QKV_N 1152
#define MROWS (B_WIN*NTOK)        // 36864
#define QSCALE 0.17677669529663689f   // 32^-0.5
#define QKV_PLANE 56623104ll          // 3072*144*128 bytes per q/k/v plane

// ---------------- Scratch (static device globals; allocation-free) ----------
__device__ char g_qkvp[169869312];            // packed q/k/v (see R6 layout)
__device__ __nv_bfloat16 g_xa_hi[14155776];   // x split, [36864][384]
__device__ __nv_bfloat16 g_xa_lo[14155776];
__device__ __nv_bfloat16 g_wqkvT_hi[442368];  // [1152][384]
__device__ __nv_bfloat16 g_wqkvT_lo[442368];
__device__ __nv_bfloat16 g_woutT_hi[147456];  // [384][384]
__device__ __nv_bfloat16 g_woutT_lo[147456];
__device__ __nv_bfloat16 g_att_hi[14155776];  // attention out split, [36864][384]
__device__ __nv_bfloat16 g_att_lo[14155776];

// ---------------- helpers ---------------------------------------------------
__device__ __forceinline__ uint32_t smem_u32(const void* p) {
    return (uint32_t)__cvta_generic_to_shared(p);
}
__device__ __forceinline__ uint32_t pack_bf2(__nv_bfloat16 a, __nv_bfloat16 b) {
    return (uint32_t)__bfloat16_as_ushort(a) | ((uint32_t)__bfloat16_as_ushort(b) << 16);
}
__device__ __forceinline__ void ldsm_x4(uint32_t* r, uint32_t addr) {
    asm volatile("ldmatrix.sync.aligned.m8n8.x4.shared.b16 {%0,%1,%2,%3}, [%4];"
                 : "=r"(r[0]), "=r"(r[1]), "=r"(r[2]), "=r"(r[3]) : "r"(addr));
}
__device__ __forceinline__ void ldsm_x4_t(uint32_t* r, uint32_t addr) {
    asm volatile("ldmatrix.sync.aligned.m8n8.x4.trans.shared.b16 {%0,%1,%2,%3}, [%4];"
                 : "=r"(r[0]), "=r"(r[1]), "=r"(r[2]), "=r"(r[3]) : "r"(addr));
}
__device__ __forceinline__ void mma_bf16(float* c, const uint32_t* a, const uint32_t* b) {
    asm volatile(
        "mma.sync.aligned.m16n8k16.row.col.f32.bf16.bf16.f32 "
        "{%0,%1,%2,%3}, {%4,%5,%6,%7}, {%8,%9}, {%0,%1,%2,%3};"
        : "+f"(c[0]), "+f"(c[1]), "+f"(c[2]), "+f"(c[3])
        : "r"(a[0]), "r"(a[1]), "r"(a[2]), "r"(a[3]), "r"(b[0]), "r"(b[1]));
}
__device__ __forceinline__ void cp_async16(uint32_t s, const void* g) {
    asm volatile("cp.async.cg.shared.global [%0], [%1], 16;" :: "r"(s), "l"(g));
}
#define CP_COMMIT() asm volatile("cp.async.commit_group;" ::: "memory")
#define CP_WAIT1()  asm volatile("cp.async.wait_group 1;" ::: "memory")
#define CP_WAIT0()  asm volatile("cp.async.wait_group 0;" ::: "memory")

// ---------------------------------------------------------------------------
// Prep kernels
// ---------------------------------------------------------------------------
__global__ void convert_x_kernel(const float* __restrict__ x,
                                 __nv_bfloat16* __restrict__ hi,
                                 __nv_bfloat16* __restrict__ lo, int n4)
{
    int idx = blockIdx.x * blockDim.x + threadIdx.x;
    int stride = gridDim.x * blockDim.x;
    for (; idx < n4; idx += stride) {
        float4 v = ((const float4*)x)[idx];
        __nv_bfloat16 h0 = __float2bfloat16(v.x);
        __nv_bfloat16 h1 = __float2bfloat16(v.y);
        __nv_bfloat16 h2 = __float2bfloat16(v.z);
        __nv_bfloat16 h3 = __float2bfloat16(v.w);
        __nv_bfloat16 l0 = __float2bfloat16(v.x - __bfloat162float(h0));
        __nv_bfloat16 l1 = __float2bfloat16(v.y - __bfloat162float(h1));
        __nv_bfloat16 l2 = __float2bfloat16(v.z - __bfloat162float(h2));
        __nv_bfloat16 l3 = __float2bfloat16(v.w - __bfloat162float(h3));
        ((uint2*)hi)[idx] = make_uint2(pack_bf2(h0, h1), pack_bf2(h2, h3));
        ((uint2*)lo)[idx] = make_uint2(pack_bf2(l0, l1), pack_bf2(l2, l3));
    }
}

__global__ void convert_wT_kernel(const float* __restrict__ w,
                                  __nv_bfloat16* __restrict__ hi,
                                  __nv_bfloat16* __restrict__ lo,
                                  int K, int Nn)
{
    int idx = blockIdx.x * blockDim.x + threadIdx.x;
    int total = K * Nn;
    if (idx >= total) return;
    int n = idx / K, k = idx - n * K;
    float v = w[(size_t)k * Nn + n];
    __nv_bfloat16 h = __float2bfloat16(v);
    __nv_bfloat16 l = __float2bfloat16(v - __bfloat162float(h));
    hi[idx] = h;
    lo[idx] = l;
}

// ---------------------------------------------------------------------------
// HMMA split-bf16 GEMM, BK=32, 3-stage cp.async, 2 CTAs/SM.
// D(128x128) = A(128x384) @ B^T(128x384), fp32 accum.
// Tile: 128 rows x 32 bf16 (64B row, 4 chunks); swizzle phys = l ^ ((r>>1)&3).
// smem: 3 stages x 4 tiles x 8KB = 96KB.
// mode 0: qkv epilogue -> packed bf16 hi/lo q/k/v planes (+bias, q-scale)
// mode 1: out epilogue (bias, write fp32 out)
// ---------------------------------------------------------------------------
#define TB32 8192
#define STG32 (4 * TB32)
#define NKC 12

__global__ __launch_bounds__(256, 2)
void hmma_gemm_kernel(const __nv_bfloat16* __restrict__ Ah,
                      const __nv_bfloat16* __restrict__ Al,
                      const __nv_bfloat16* __restrict__ Bh,
                      const __nv_bfloat16* __restrict__ Bl,
                      const float* __restrict__ bias,
                      float* __restrict__ outp, int mode)
{
    extern __shared__ char smem[];
    const uint32_t usm = smem_u32(smem);

    const int tid = threadIdx.x;
    const int wid = tid >> 5, lane = tid & 31;
    const int bm = blockIdx.y * 128;
    const int bn = blockIdx.x * 128;
    const int wm = wid >> 2, wn = wid & 3;
    const int m0w = wm * 64, n0w = wn * 32;

    // load geometry: 512 lines/tile, 2 iters; r = v>>2, c = v&3
    const int r0l = tid >> 2;            // rows 0..63 (iter 0), +64 (iter 1)
    const int c0l = tid & 3;

    float acc[4][4][4];
#pragma unroll
    for (int mt = 0; mt < 4; mt++)
#pragma unroll
        for (int nt = 0; nt < 4; nt++)
#pragma unroll
            for (int e = 0; e < 4; e++) acc[mt][nt][e] = 0.f;

    const int lr = lane & 15;
    const int lc = lane >> 4;

#define LOAD_STAGE32(kc, buf)                                                   \
    {                                                                           \
        uint32_t s0 = usm + (buf) * STG32;                                      \
        _Pragma("unroll")                                                       \
        for (int it = 0; it < 2; it++) {                                        \
            int r = r0l + it * 64;                                              \
            size_t gA = (size_t)(bm + r) * 384 + (kc) * 32 + c0l * 8;           \
            size_t gB = (size_t)(bn + r) * 384 + (kc) * 32 + c0l * 8;           \
            uint32_t d = r * 64 + ((c0l ^ ((r >> 1) & 3)) * 16);                \
            cp_async16(s0 + d, Ah + gA);                                        \
            cp_async16(s0 + TB32 + d, Al + gA);                                 \
            cp_async16(s0 + 2 * TB32 + d, Bh + gB);                             \
            cp_async16(s0 + 3 * TB32 + d, Bl + gB);                             \
        }                                                                       \
        CP_COMMIT();                                                            \
    }

    LOAD_STAGE32(0, 0);
    LOAD_STAGE32(1, 1);

    int buf = 0;
    for (int kc = 0; kc < NKC; kc++) {
        if (kc < NKC - 1) { CP_WAIT1(); } else { CP_WAIT0(); }
        __syncthreads();
        if (kc + 2 < NKC) {
            int nb = buf + 2; if (nb >= 3) nb -= 3;
            LOAD_STAGE32(kc + 2, nb);
        }

        const uint32_t uAh = usm + buf * STG32;
        const uint32_t uAl = uAh + TB32;
        const uint32_t uBh = uAh + 2 * TB32;
        const uint32_t uBl = uAh + 3 * TB32;

#pragma unroll
        for (int k16 = 0; k16 < 2; k16++) {
            const int chunk = k16 * 2 + lc;
            uint32_t aH[4][4], aL[4][4];
            uint32_t bH[4][2], bL[4][2];
#pragma unroll
            for (int mt = 0; mt < 4; mt++) {
                int r = m0w + mt * 16 + lr;
                uint32_t off = r * 64 + ((chunk ^ ((r >> 1) & 3)) * 16);
                ldsm_x4(aH[mt], uAh + off);
                ldsm_x4(aL[mt], uAl + off);
            }
#pragma unroll
            for (int np = 0; np < 2; np++) {
                int r = n0w + np * 16 + lr;
                uint32_t off = r * 64 + ((chunk ^ ((r >> 1) & 3)) * 16);
                uint32_t t[4];
                ldsm_x4(t, uBh + off);
                bH[2 * np][0] = t[0]; bH[2 * np][1] = t[2];
                bH[2 * np + 1][0] = t[1]; bH[2 * np + 1][1] = t[3];
                ldsm_x4(t, uBl + off);
                bL[2 * np][0] = t[0]; bL[2 * np][1] = t[2];
                bL[2 * np + 1][0] = t[1]; bL[2 * np + 1][1] = t[3];
            }
#pragma unroll
            for (int mt = 0; mt < 4; mt++)
#pragma unroll
                for (int nt = 0; nt < 4; nt++) {
                    mma_bf16(acc[mt][nt], aH[mt], bH[nt]);
                    mma_bf16(acc[mt][nt], aH[mt], bL[nt]);
                    mma_bf16(acc[mt][nt], aL[mt], bH[nt]);
                }
        }
        __syncthreads();
        if (++buf == 3) buf = 0;
    }
#undef LOAD_STAGE32

    if (mode == 0) {
#pragma unroll
        for (int mt = 0; mt < 4; mt++) {
#pragma unroll
            for (int nt = 0; nt < 4; nt++) {
                int col = bn + n0w + nt * 8 + (lane & 3) * 2;
                int s = col / 384;
                int rem = col - s * 384;
                int hh = rem >> 5, d = rem & 31;
                float sc = (s == 0) ? QSCALE : 1.0f;
                float b0 = bias[col], b1 = bias[col + 1];
                char* plane = g_qkvp + (size_t)s * QKV_PLANE;
                int lH = d >> 3, lL = 4 + (d >> 3);
                int byt = (d & 7) * 2;
#pragma unroll
                for (int half = 0; half < 2; half++) {
                    int row = bm + m0w + mt * 16 + (lane >> 2) + half * 8;
                    int b = row / 144, i = row - b * 144;
                    float v0 = (acc[mt][nt][half * 2 + 0] + b0) * sc;
                    float v1 = (acc[mt][nt][half * 2 + 1] + b1) * sc;
                    __nv_bfloat16 h0 = __float2bfloat16(v0);
                    __nv_bfloat16 h1 = __float2bfloat16(v1);
                    uint32_t hiW = pack_bf2(h0, h1);
                    uint32_t loW = pack_bf2(__float2bfloat16(v0 - __bfloat162float(h0)),
                                            __float2bfloat16(v1 - __bfloat162float(h1)));
                    char* base = plane + ((size_t)(b * 12 + hh) * 144 + i) * 128;
                    *(uint32_t*)(base + ((lH ^ (i & 7)) * 16) + byt) = hiW;
                    *(uint32_t*)(base + ((lL ^ (i & 7)) * 16) + byt) = loW;
                }
            }
        }
    } else {
#pragma unroll
        for (int mt = 0; mt < 4; mt++) {
#pragma unroll
            for (int nt = 0; nt < 4; nt++) {
                int col = bn + n0w + nt * 8 + (lane & 3) * 2;
                float b0 = bias[col], b1 = bias[col + 1];
#pragma unroll
                for (int half = 0; half < 2; half++) {
                    int row = bm + m0w + mt * 16 + (lane >> 2) + half * 8;
                    float2 v;
                    v.x = acc[mt][nt][half * 2 + 0] + b0;
                    v.y = acc[mt][nt][half * 2 + 1] + b1;
                    *(float2*)(outp + (size_t)row * 384 + col) = v;
                }
            }
        }
    }
}

// ---------------------------------------------------------------------------
// Flash-style HMMA attention (unchanged from R6)
// ---------------------------------------------------------------------------
__global__ __launch_bounds__(288, 1)
void attn_mma_kernel(const float* __restrict__ mask,
                     const float* __restrict__ bias_table,
                     const int*   __restrict__ pos_idx)
{
    extern __shared__ char sm[];
    char* sQ = sm;
    char* sK = sm + 18432;
    char* sV = sm + 36864;
    float* sB = (float*)(sm + 55296);
    const uint32_t uQ = smem_u32(sQ), uK = smem_u32(sK), uV = smem_u32(sV);

    const int bh = blockIdx.x;
    const int b = bh / HEADS, h = bh - b * HEADS;
    const int g  = b >> 5;
    const int t  = b & 31;
    const int mw = b & 7;

    const int tid = threadIdx.x;
    const int wid = tid >> 5, lane = tid & 31;

    {
        const uint4* q = (const uint4*)(g_qkvp + (size_t)bh * 18432);
        const uint4* k = (const uint4*)(g_qkvp + QKV_PLANE + (size_t)bh * 18432);
        const uint4* v = (const uint4*)(g_qkvp + 2 * QKV_PLANE + (size_t)bh * 18432);
        uint4* dq = (uint4*)sQ; uint4* dk = (uint4*)sK; uint4* dv = (uint4*)sV;
        for (int i = tid; i < 1152; i += 288) { dq[i] = q[i]; dk[i] = k[i]; dv[i] = v[i]; }
    }
    for (int s = tid; s < 2592; s += 288)
        sB[s] = bias_table[(size_t)pos_idx[8 * s + g] * (32 * HEADS) + t * HEADS + h];
    __syncthreads();

    const int m0 = wid * 16;
    const int gr = lane >> 2, q2 = lane & 3;
    const int i0 = m0 + gr, i1 = i0 + 8;

    float c[18][4];
    {
        const float* mrow0 = mask + ((size_t)mw * 144 + i0) * 144;
        const float* mrow1 = mask + ((size_t)mw * 144 + i1) * 144;
        const float* brow0 = sB + (i0 % 18) * 144;
        const float* brow1 = sB + (i1 % 18) * 144;
#pragma unroll
        for (int nt = 0; nt < 18; nt++) {
            int j = nt * 8 + q2 * 2;
            float2 mv0 = *(const float2*)(mrow0 + j);
            float2 mv1 = *(const float2*)(mrow1 + j);
            float2 bv0 = *(const float2*)(brow0 + j);
            float2 bv1 = *(const float2*)(brow1 + j);
            c[nt][0] = mv0.x + bv0.x; c[nt][1] = mv0.y + bv0.y;
            c[nt][2] = mv1.x + bv1.x; c[nt][3] = mv1.y + bv1.y;
        }
    }

    const int lr = lane & 15, lc = lane >> 4;
#pragma unroll
    for (int kk = 0; kk < 2; kk++) {
        uint32_t aH[4], aL[4];
        {
            int r = m0 + lr;
            int lH = kk * 2 + lc, lL = lH + 4;
            ldsm_x4(aH, uQ + r * 128 + ((lH ^ (r & 7)) * 16));
            ldsm_x4(aL, uQ + r * 128 + ((lL ^ (r & 7)) * 16));
        }
#pragma unroll
        for (int np = 0; np < 9; np++) {
            int r = np * 16 + lr;
            int lH = kk * 2 + lc, lL = lH + 4;
            uint32_t tH[4], tL[4];
            ldsm_x4(tH, uK + r * 128 + ((lH ^ (r & 7)) * 16));
            ldsm_x4(tL, uK + r * 128 + ((lL ^ (r & 7)) * 16));
            uint32_t b0H[2] = {tH[0], tH[2]}, b1H[2] = {tH[1], tH[3]};
            uint32_t b0L[2] = {tL[0], tL[2]}, b1L[2] = {tL[1], tL[3]};
            mma_bf16(c[2 * np],     aH, b0H);
            mma_bf16(c[2 * np],     aH, b0L);
            mma_bf16(c[2 * np],     aL, b0H);
            mma_bf16(c[2 * np + 1], aH, b1H);
            mma_bf16(c[2 * np + 1], aH, b1L);
            mma_bf16(c[2 * np + 1], aL, b1H);
        }
    }

    float mx0 = -1e30f, mx1 = -1e30f;
#pragma unroll
    for (int nt = 0; nt < 18; nt++) {
        mx0 = fmaxf(mx0, fmaxf(c[nt][0], c[nt][1]));
        mx1 = fmaxf(mx1, fmaxf(c[nt][2], c[nt][3]));
    }
    mx0 = fmaxf(mx0, __shfl_xor_sync(0xffffffffu, mx0, 1));
    mx0 = fmaxf(mx0, __shfl_xor_sync(0xffffffffu, mx0, 2));
    mx1 = fmaxf(mx1, __shfl_xor_sync(0xffffffffu, mx1, 1));
    mx1 = fmaxf(mx1, __shfl_xor_sync(0xffffffffu, mx1, 2));
    float s0 = 0.f, s1 = 0.f;
#pragma unroll
    for (int nt = 0; nt < 18; nt++) {
        c[nt][0] = __expf(c[nt][0] - mx0); s0 += c[nt][0];
        c[nt][1] = __expf(c[nt][1] - mx0); s0 += c[nt][1];
        c[nt][2] = __expf(c[nt][2] - mx1); s1 += c[nt][2];
        c[nt][3] = __expf(c[nt][3] - mx1); s1 += c[nt][3];
    }
    s0 += __shfl_xor_sync(0xffffffffu, s0, 1);
    s0 += __shfl_xor_sync(0xffffffffu, s0, 2);
    s1 += __shfl_xor_sync(0xffffffffu, s1, 1);
    s1 += __shfl_xor_sync(0xffffffffu, s1, 2);
    float inv0 = 1.f / s0, inv1 = 1.f / s1;
#pragma unroll
    for (int nt = 0; nt < 18; nt++) {
        c[nt][0] *= inv0; c[nt][1] *= inv0;
        c[nt][2] *= inv1; c[nt][3] *= inv1;
    }

    float o[4][4];
#pragma unroll
    for (int ng = 0; ng < 4; ng++)
#pragma unroll
        for (int e = 0; e < 4; e++) o[ng][e] = 0.f;

    const int grp = lane >> 3, wi = lane & 7;
#pragma unroll
    for (int kk = 0; kk < 9; kk++) {
        uint32_t ah[4], al[4];
#pragma unroll
        for (int p = 0; p < 4; p++) {
            const float x = c[(p < 2) ? 2 * kk : 2 * kk + 1][(p & 1) * 2 + 0];
            const float y = c[(p < 2) ? 2 * kk : 2 * kk + 1][(p & 1) * 2 + 1];
            __nv_bfloat16 hx = __float2bfloat16(x);
            __nv_bfloat16 hy = __float2bfloat16(y);
            ah[p] = pack_bf2(hx, hy);
            al[p] = pack_bf2(__float2bfloat16(x - __bfloat162float(hx)),
                             __float2bfloat16(y - __bfloat162float(hy)));
        }
        int r = kk * 16 + (grp & 1) * 8 + wi;
#pragma unroll
        for (int ncp = 0; ncp < 2; ncp++) {
            int lH = ncp * 2 + (grp >> 1), lL = lH + 4;
            uint32_t th[4], tl[4];
            ldsm_x4_t(th, uV + r * 128 + ((lH ^ (r & 7)) * 16));
            ldsm_x4_t(tl, uV + r * 128 + ((lL ^ (r & 7)) * 16));
            uint32_t bh0[2] = {th[0], th[1]}, bh1[2] = {th[2], th[3]};
            uint32_t bl0[2] = {tl[0], tl[1]}, bl1[2] = {tl[2], tl[3]};
            mma_bf16(o[ncp * 2],     ah, bh0);
            mma_bf16(o[ncp * 2],     ah, bl0);
            mma_bf16(o[ncp * 2],     al, bh0);
            mma_bf16(o[ncp * 2 + 1], ah, bh1);
            mma_bf16(o[ncp * 2 + 1], ah, bl1);
            mma_bf16(o[ncp * 2 + 1], al, bh1);
        }
    }

#pragma unroll
    for (int ng = 0; ng < 4; ng++) {
        int d = ng * 8 + q2 * 2;
        int col = h * 32 + d;
        size_t r0o = ((size_t)b * 144 + i0) * 384 + col;
        size_t r1o = ((size_t)b * 144 + i1) * 384 + col;
        __nv_bfloat16 h0 = __float2bfloat16(o[ng][0]);
        __nv_bfloat16 h1 = __float2bfloat16(o[ng][1]);
        __nv_bfloat16 h2 = __float2bfloat16(o[ng][2]);
        __nv_bfloat16 h3 = __float2bfloat16(o[ng][3]);
        *(uint32_t*)(g_att_hi + r0o) = pack_bf2(h0, h1);
        *(uint32_t*)(g_att_hi + r1o) = pack_bf2(h2, h3);
        *(uint32_t*)(g_att_lo + r0o) =
            pack_bf2(__float2bfloat16(o[ng][0] - __bfloat162float(h0)),
                     __float2bfloat16(o[ng][1] - __bfloat162float(h1)));
        *(uint32_t*)(g_att_lo + r1o) =
            pack_bf2(__float2bfloat16(o[ng][2] - __bfloat162float(h2)),
                     __float2bfloat16(o[ng][3] - __bfloat162float(h3)));
    }
}

// ---------------------------------------------------------------------------
extern "C" void kernel_launch(void* const* d_in, const int* in_sizes, int n_in,
                              void* d_out, int out_size)
{
    const float* x          = (const float*)d_in[0];
    const float* mask       = (const float*)d_in[1];
    const float* w_qkv      = (const float*)d_in[2];
    const float* b_qkv      = (const float*)d_in[3];
    const float* w_out      = (const float*)d_in[4];
    const float* b_out      = (const float*)d_in[5];
    const float* bias_table = (const float*)d_in[6];
    const int*   pos_idx    = (const int*)d_in[7];
    float* out = (float*)d_out;

    __nv_bfloat16 *xa_hi, *xa_lo, *wqT_hi, *wqT_lo, *woT_hi, *woT_lo;
    __nv_bfloat16 *att_hi, *att_lo;
    cudaGetSymbolAddress((void**)&xa_hi, g_xa_hi);
    cudaGetSymbolAddress((void**)&xa_lo, g_xa_lo);
    cudaGetSymbolAddress((void**)&wqT_hi, g_wqkvT_hi);
    cudaGetSymbolAddress((void**)&wqT_lo, g_wqkvT_lo);
    cudaGetSymbolAddress((void**)&woT_hi, g_woutT_hi);
    cudaGetSymbolAddress((void**)&woT_lo, g_woutT_lo);
    cudaGetSymbolAddress((void**)&att_hi, g_att_hi);
    cudaGetSymbolAddress((void**)&att_lo, g_att_lo);

    const int smem_gemm = 3 * STG32;  // 96 KB
    cudaFuncSetAttribute(hmma_gemm_kernel, cudaFuncAttributeMaxDynamicSharedMemorySize,
                         smem_gemm);
    const int smem_attn = 3 * 18432 + 2592 * 4;  // 65664
    cudaFuncSetAttribute(attn_mma_kernel, cudaFuncAttributeMaxDynamicSharedMemorySize,
                         smem_attn);

    convert_x_kernel<<<2048, 256>>>(x, xa_hi, xa_lo, MROWS * DIM / 4);
    convert_wT_kernel<<<(DIM * QKV_N + 255) / 256, 256>>>(w_qkv, wqT_hi, wqT_lo,
                                                          DIM, QKV_N);
    convert_wT_kernel<<<(DIM * DIM + 255) / 256, 256>>>(w_out, woT_hi, woT_lo,
                                                        DIM, DIM);
    // qkv projection -> packed q/k/v
    hmma_gemm_kernel<<<dim3(QKV_N / 128, MROWS / 128), 256, smem_gemm>>>(
        xa_hi, xa_lo, wqT_hi, wqT_lo, b_qkv, nullptr, 0);
    // attention
    attn_mma_kernel<<<B_WIN * HEADS, 288, smem_attn>>>(mask, bias_table, pos_idx);
    // output projection
    hmma_gemm_kernel<<<dim3(DIM / 128, MROWS / 128), 256, smem_gemm>>>(
        att_hi, att_lo, woT_hi, woT_lo, b_out, out, 1);
}

// round 10
// speedup vs baseline: 1.2632x; 1.2268x over previous
#include <cuda_runtime.h>
#include <cuda_fp16.h>
#include <cstdint>

// Problem constants
#define B_WIN 256
#define NTOK  144
#define DIM   384
#define HEADS 12
#define HD    32
#define QKV_N 1152
#define MROWS (B_WIN*NTOK)        // 36864
#define QSCALE 0.17677669529663689f   // 32^-0.5

// Packed planes inside g_qkvp:
//  Q: [3072 bh][144 rows][128B]  (chunks 0-3 = fp16 hi d0..31, 4-7 = fp16 lo,
//                                 swizzle phys = l ^ (row&7))
//  K: [3072 bh][144 rows][64B]   (single fp16, 4 chunks, phys = c ^ ((r>>1)&3))
//  V: same as K
#define Q_OFF 0ll
#define K_OFF 56623104ll
#define V_OFF 84934656ll

// ---------------- Scratch (static device globals; allocation-free) ----------
__device__ char   g_qkvp[169869312];
__device__ __half g_xa_hi[14155776];   // x split, [36864][384]
__device__ __half g_xa_lo[14155776];
__device__ __half g_wqkvT[442368];     // [1152][384] single fp16
__device__ __half g_woutT[147456];     // [384][384] single fp16
__device__ __half g_att_hi[14155776];  // attention out split, [36864][384]
__device__ __half g_att_lo[14155776];

// ---------------- helpers ---------------------------------------------------
__device__ __forceinline__ uint32_t smem_u32(const void* p) {
    return (uint32_t)__cvta_generic_to_shared(p);
}
__device__ __forceinline__ uint32_t pack_h2(__half a, __half b) {
    return (uint32_t)__half_as_ushort(a) | ((uint32_t)__half_as_ushort(b) << 16);
}
__device__ __forceinline__ void ldsm_x4(uint32_t* r, uint32_t addr) {
    asm volatile("ldmatrix.sync.aligned.m8n8.x4.shared.b16 {%0,%1,%2,%3}, [%4];"
                 : "=r"(r[0]), "=r"(r[1]), "=r"(r[2]), "=r"(r[3]) : "r"(addr));
}
__device__ __forceinline__ void ldsm_x4_t(uint32_t* r, uint32_t addr) {
    asm volatile("ldmatrix.sync.aligned.m8n8.x4.trans.shared.b16 {%0,%1,%2,%3}, [%4];"
                 : "=r"(r[0]), "=r"(r[1]), "=r"(r[2]), "=r"(r[3]) : "r"(addr));
}
__device__ __forceinline__ void mma_f16(float* c, const uint32_t* a, const uint32_t* b) {
    asm volatile(
        "mma.sync.aligned.m16n8k16.row.col.f32.f16.f16.f32 "
        "{%0,%1,%2,%3}, {%4,%5,%6,%7}, {%8,%9}, {%0,%1,%2,%3};"
        : "+f"(c[0]), "+f"(c[1]), "+f"(c[2]), "+f"(c[3])
        : "r"(a[0]), "r"(a[1]), "r"(a[2]), "r"(a[3]), "r"(b[0]), "r"(b[1]));
}
__device__ __forceinline__ void cp_async16(uint32_t s, const void* g) {
    asm volatile("cp.async.cg.shared.global [%0], [%1], 16;" :: "r"(s), "l"(g));
}
#define CP_COMMIT() asm volatile("cp.async.commit_group;" ::: "memory")
#define CP_WAIT1()  asm volatile("cp.async.wait_group 1;" ::: "memory")
#define CP_WAIT0()  asm volatile("cp.async.wait_group 0;" ::: "memory")

// ---------------------------------------------------------------------------
// Prep kernels
// ---------------------------------------------------------------------------
__global__ void convert_x_kernel(const float* __restrict__ x,
                                 __half* __restrict__ hi,
                                 __half* __restrict__ lo, int n4)
{
    int idx = blockIdx.x * blockDim.x + threadIdx.x;
    int stride = gridDim.x * blockDim.x;
    for (; idx < n4; idx += stride) {
        float4 v = ((const float4*)x)[idx];
        __half h0 = __float2half_rn(v.x);
        __half h1 = __float2half_rn(v.y);
        __half h2 = __float2half_rn(v.z);
        __half h3 = __float2half_rn(v.w);
        __half l0 = __float2half_rn(v.x - __half2float(h0));
        __half l1 = __float2half_rn(v.y - __half2float(h1));
        __half l2 = __float2half_rn(v.z - __half2float(h2));
        __half l3 = __float2half_rn(v.w - __half2float(h3));
        ((uint2*)hi)[idx] = make_uint2(pack_h2(h0, h1), pack_h2(h2, h3));
        ((uint2*)lo)[idx] = make_uint2(pack_h2(l0, l1), pack_h2(l2, l3));
    }
}

// transpose weight w[K][Nn] -> wT[Nn][K] single fp16
__global__ void convert_wT_kernel(const float* __restrict__ w,
                                  __half* __restrict__ dst, int K, int Nn)
{
    int idx = blockIdx.x * blockDim.x + threadIdx.x;
    int total = K * Nn;
    if (idx >= total) return;
    int n = idx / K, k = idx - n * K;
    dst[idx] = __float2half_rn(w[(size_t)k * Nn + n]);
}

// ---------------------------------------------------------------------------
// HMMA fp16 2-term GEMM, BK=32, 3-stage cp.async, 2 CTAs/SM.
// D(128x128) = (Ah+Al)(128x384) @ B^T(128x384), fp32 accum.
// Tiles: Ah, Al, B — 128 rows x 32 fp16 (64B row); swizzle phys = c ^ ((r>>1)&3).
// smem: 3 stages x 3 tiles x 8KB = 72KB.
// mode 0: qkv epilogue -> packed q (hi/lo) / k / v planes (+bias, q-scale)
// mode 1: out epilogue (bias, write fp32 out)
// ---------------------------------------------------------------------------
#define TB32 8192
#define STG32 (3 * TB32)
#define NKC 12

__global__ __launch_bounds__(256, 2)
void hmma_gemm_kernel(const __half* __restrict__ Ah,
                      const __half* __restrict__ Al,
                      const __half* __restrict__ Bs,
                      const float* __restrict__ bias,
                      float* __restrict__ outp, int mode)
{
    extern __shared__ char smem[];
    const uint32_t usm = smem_u32(smem);

    const int tid = threadIdx.x;
    const int wid = tid >> 5, lane = tid & 31;
    const int bm = blockIdx.y * 128;
    const int bn = blockIdx.x * 128;
    const int wm = wid >> 2, wn = wid & 3;
    const int m0w = wm * 64, n0w = wn * 32;

    const int r0l = tid >> 2;            // rows 0..63 (iter 0), +64 (iter 1)
    const int c0l = tid & 3;

    float acc[4][4][4];
#pragma unroll
    for (int mt = 0; mt < 4; mt++)
#pragma unroll
        for (int nt = 0; nt < 4; nt++)
#pragma unroll
            for (int e = 0; e < 4; e++) acc[mt][nt][e] = 0.f;

    const int lr = lane & 15;
    const int lc = lane >> 4;

#define LOAD_STAGE32(kc, buf)                                                   \
    {                                                                           \
        uint32_t s0 = usm + (buf) * STG32;                                      \
        _Pragma("unroll")                                                       \
        for (int it = 0; it < 2; it++) {                                        \
            int r = r0l + it * 64;                                              \
            size_t gA = (size_t)(bm + r) * 384 + (kc) * 32 + c0l * 8;           \
            size_t gB = (size_t)(bn + r) * 384 + (kc) * 32 + c0l * 8;           \
            uint32_t d = r * 64 + ((c0l ^ ((r >> 1) & 3)) * 16);                \
            cp_async16(s0 + d, Ah + gA);                                        \
            cp_async16(s0 + TB32 + d, Al + gA);                                 \
            cp_async16(s0 + 2 * TB32 + d, Bs + gB);                             \
        }                                                                       \
        CP_COMMIT();                                                            \
    }

    LOAD_STAGE32(0, 0);
    LOAD_STAGE32(1, 1);

    int buf = 0;
    for (int kc = 0; kc < NKC; kc++) {
        if (kc < NKC - 1) { CP_WAIT1(); } else { CP_WAIT0(); }
        __syncthreads();
        if (kc + 2 < NKC) {
            int nb = buf + 2; if (nb >= 3) nb -= 3;
            LOAD_STAGE32(kc + 2, nb);
        }

        const uint32_t uAh = usm + buf * STG32;
        const uint32_t uAl = uAh + TB32;
        const uint32_t uB  = uAh + 2 * TB32;

#pragma unroll
        for (int k16 = 0; k16 < 2; k16++) {
            const int chunk = k16 * 2 + lc;
            uint32_t aH[4][4], aL[4][4];
            uint32_t bF[4][2];
#pragma unroll
            for (int mt = 0; mt < 4; mt++) {
                int r = m0w + mt * 16 + lr;
                uint32_t off = r * 64 + ((chunk ^ ((r >> 1) & 3)) * 16);
                ldsm_x4(aH[mt], uAh + off);
                ldsm_x4(aL[mt], uAl + off);
            }
#pragma unroll
            for (int np = 0; np < 2; np++) {
                int r = n0w + np * 16 + lr;
                uint32_t off = r * 64 + ((chunk ^ ((r >> 1) & 3)) * 16);
                uint32_t t[4];
                ldsm_x4(t, uB + off);
                bF[2 * np][0] = t[0]; bF[2 * np][1] = t[2];
                bF[2 * np + 1][0] = t[1]; bF[2 * np + 1][1] = t[3];
            }
#pragma unroll
            for (int mt = 0; mt < 4; mt++)
#pragma unroll
                for (int nt = 0; nt < 4; nt++) {
                    mma_f16(acc[mt][nt], aH[mt], bF[nt]);
                    mma_f16(acc[mt][nt], aL[mt], bF[nt]);
                }
        }
        __syncthreads();
        if (++buf == 3) buf = 0;
    }
#undef LOAD_STAGE32

    if (mode == 0) {
#pragma unroll
        for (int mt = 0; mt < 4; mt++) {
#pragma unroll
            for (int nt = 0; nt < 4; nt++) {
                int col = bn + n0w + nt * 8 + (lane & 3) * 2;
                int s = col / 384;
                int rem = col - s * 384;
                int hh = rem >> 5, d = rem & 31;
                float b0 = bias[col], b1 = bias[col + 1];
#pragma unroll
                for (int half2_ = 0; half2_ < 2; half2_++) {
                    int row = bm + m0w + mt * 16 + (lane >> 2) + half2_ * 8;
                    int b = row / 144, i = row - b * 144;
                    float v0 = acc[mt][nt][half2_ * 2 + 0] + b0;
                    float v1 = acc[mt][nt][half2_ * 2 + 1] + b1;
                    if (s == 0) {
                        v0 *= QSCALE; v1 *= QSCALE;
                        __half h0 = __float2half_rn(v0);
                        __half h1 = __float2half_rn(v1);
                        uint32_t hiW = pack_h2(h0, h1);
                        uint32_t loW = pack_h2(__float2half_rn(v0 - __half2float(h0)),
                                               __float2half_rn(v1 - __half2float(h1)));
                        char* base = g_qkvp + Q_OFF +
                                     ((size_t)(b * 12 + hh) * 144 + i) * 128;
                        int lH = d >> 3, lL = 4 + (d >> 3);
                        int byt = (d & 7) * 2;
                        *(uint32_t*)(base + ((lH ^ (i & 7)) * 16) + byt) = hiW;
                        *(uint32_t*)(base + ((lL ^ (i & 7)) * 16) + byt) = loW;
                    } else {
                        char* plane = g_qkvp + ((s == 1) ? K_OFF : V_OFF);
                        char* base = plane + ((size_t)(b * 12 + hh) * 144 + i) * 64;
                        int ch = d >> 3;
                        int byt = (d & 7) * 2;
                        uint32_t w = pack_h2(__float2half_rn(v0), __float2half_rn(v1));
                        *(uint32_t*)(base + ((ch ^ ((i >> 1) & 3)) * 16) + byt) = w;
                    }
                }
            }
        }
    } else {
#pragma unroll
        for (int mt = 0; mt < 4; mt++) {
#pragma unroll
            for (int nt = 0; nt < 4; nt++) {
                int col = bn + n0w + nt * 8 + (lane & 3) * 2;
                float b0 = bias[col], b1 = bias[col + 1];
#pragma unroll
                for (int half2_ = 0; half2_ < 2; half2_++) {
                    int row = bm + m0w + mt * 16 + (lane >> 2) + half2_ * 8;
                    float2 v;
                    v.x = acc[mt][nt][half2_ * 2 + 0] + b0;
                    v.y = acc[mt][nt][half2_ * 2 + 1] + b1;
                    *(float2*)(outp + (size_t)row * 384 + col) = v;
                }
            }
        }
    }
}

// ---------------------------------------------------------------------------
// Flash-style HMMA attention, fp16 2-term.
// Q split hi/lo (128B rows), K/V single fp16 (64B rows).
// ---------------------------------------------------------------------------
__global__ __launch_bounds__(288, 1)
void attn_mma_kernel(const float* __restrict__ mask,
                     const float* __restrict__ bias_table,
                     const int*   __restrict__ pos_idx)
{
    extern __shared__ char sm[];
    char* sQ = sm;                     // 18432 B
    char* sK = sm + 18432;             // 9216 B
    char* sV = sm + 27648;             // 9216 B
    float* sB = (float*)(sm + 36864);  // 2592 floats
    const uint32_t uQ = smem_u32(sQ), uK = smem_u32(sK), uV = smem_u32(sV);

    const int bh = blockIdx.x;
    const int b = bh / HEADS, h = bh - b * HEADS;
    const int g  = b >> 5;
    const int t  = b & 31;
    const int mw = b & 7;

    const int tid = threadIdx.x;
    const int wid = tid >> 5, lane = tid & 31;

    {
        const uint4* q = (const uint4*)(g_qkvp + Q_OFF + (size_t)bh * 18432);
        const uint4* k = (const uint4*)(g_qkvp + K_OFF + (size_t)bh * 9216);
        const uint4* v = (const uint4*)(g_qkvp + V_OFF + (size_t)bh * 9216);
        uint4* dq = (uint4*)sQ; uint4* dk = (uint4*)sK; uint4* dv = (uint4*)sV;
        for (int i = tid; i < 1152; i += 288) dq[i] = q[i];
        for (int i = tid; i < 576; i += 288) { dk[i] = k[i]; dv[i] = v[i]; }
    }
    for (int s = tid; s < 2592; s += 288)
        sB[s] = bias_table[(size_t)pos_idx[8 * s + g] * (32 * HEADS) + t * HEADS + h];
    __syncthreads();

    const int m0 = wid * 16;
    const int gr = lane >> 2, q2 = lane & 3;
    const int i0 = m0 + gr, i1 = i0 + 8;

    float c[18][4];
    {
        const float* mrow0 = mask + ((size_t)mw * 144 + i0) * 144;
        const float* mrow1 = mask + ((size_t)mw * 144 + i1) * 144;
        const float* brow0 = sB + (i0 % 18) * 144;
        const float* brow1 = sB + (i1 % 18) * 144;
#pragma unroll
        for (int nt = 0; nt < 18; nt++) {
            int j = nt * 8 + q2 * 2;
            float2 mv0 = *(const float2*)(mrow0 + j);
            float2 mv1 = *(const float2*)(mrow1 + j);
            float2 bv0 = *(const float2*)(brow0 + j);
            float2 bv1 = *(const float2*)(brow1 + j);
            c[nt][0] = mv0.x + bv0.x; c[nt][1] = mv0.y + bv0.y;
            c[nt][2] = mv1.x + bv1.x; c[nt][3] = mv1.y + bv1.y;
        }
    }

    const int lr = lane & 15, lc = lane >> 4;
#pragma unroll
    for (int kk = 0; kk < 2; kk++) {
        uint32_t aH[4], aL[4];
        {
            int r = m0 + lr;
            int lH = kk * 2 + lc, lL = lH + 4;
            ldsm_x4(aH, uQ + r * 128 + ((lH ^ (r & 7)) * 16));
            ldsm_x4(aL, uQ + r * 128 + ((lL ^ (r & 7)) * 16));
        }
#pragma unroll
        for (int np = 0; np < 9; np++) {
            int r = np * 16 + lr;
            int ch = kk * 2 + lc;
            uint32_t tK[4];
            ldsm_x4(tK, uK + r * 64 + ((ch ^ ((r >> 1) & 3)) * 16));
            uint32_t b0[2] = {tK[0], tK[2]}, b1[2] = {tK[1], tK[3]};
            mma_f16(c[2 * np],     aH, b0);
            mma_f16(c[2 * np],     aL, b0);
            mma_f16(c[2 * np + 1], aH, b1);
            mma_f16(c[2 * np + 1], aL, b1);
        }
    }

    float mx0 = -1e30f, mx1 = -1e30f;
#pragma unroll
    for (int nt = 0; nt < 18; nt++) {
        mx0 = fmaxf(mx0, fmaxf(c[nt][0], c[nt][1]));
        mx1 = fmaxf(mx1, fmaxf(c[nt][2], c[nt][3]));
    }
    mx0 = fmaxf(mx0, __shfl_xor_sync(0xffffffffu, mx0, 1));
    mx0 = fmaxf(mx0, __shfl_xor_sync(0xffffffffu, mx0, 2));
    mx1 = fmaxf(mx1, __shfl_xor_sync(0xffffffffu, mx1, 1));
    mx1 = fmaxf(mx1, __shfl_xor_sync(0xffffffffu, mx1, 2));
    float s0 = 0.f, s1 = 0.f;
#pragma unroll
    for (int nt = 0; nt < 18; nt++) {
        c[nt][0] = __expf(c[nt][0] - mx0); s0 += c[nt][0];
        c[nt][1] = __expf(c[nt][1] - mx0); s0 += c[nt][1];
        c[nt][2] = __expf(c[nt][2] - mx1); s1 += c[nt][2];
        c[nt][3] = __expf(c[nt][3] - mx1); s1 += c[nt][3];
    }
    s0 += __shfl_xor_sync(0xffffffffu, s0, 1);
    s0 += __shfl_xor_sync(0xffffffffu, s0, 2);
    s1 += __shfl_xor_sync(0xffffffffu, s1, 1);
    s1 += __shfl_xor_sync(0xffffffffu, s1, 2);
    float inv0 = 1.f / s0, inv1 = 1.f / s1;
#pragma unroll
    for (int nt = 0; nt < 18; nt++) {
        c[nt][0] *= inv0; c[nt][1] *= inv0;
        c[nt][2] *= inv1; c[nt][3] *= inv1;
    }

    float o[4][4];
#pragma unroll
    for (int ng = 0; ng < 4; ng++)
#pragma unroll
        for (int e = 0; e < 4; e++) o[ng][e] = 0.f;

    const int grp = lane >> 3, wi = lane & 7;
#pragma unroll
    for (int kk = 0; kk < 9; kk++) {
        // P frags hi/lo fp16 from score frags
        uint32_t ah[4], al[4];
#pragma unroll
        for (int p = 0; p < 4; p++) {
            const float x = c[(p < 2) ? 2 * kk : 2 * kk + 1][(p & 1) * 2 + 0];
            const float y = c[(p < 2) ? 2 * kk : 2 * kk + 1][(p & 1) * 2 + 1];
            __half hx = __float2half_rn(x);
            __half hy = __float2half_rn(y);
            ah[p] = pack_h2(hx, hy);
            al[p] = pack_h2(__float2half_rn(x - __half2float(hx)),
                            __float2half_rn(y - __half2float(hy)));
        }
        int r = kk * 16 + (grp & 1) * 8 + wi;
#pragma unroll
        for (int ncp = 0; ncp < 2; ncp++) {
            int ch = ncp * 2 + (grp >> 1);
            uint32_t tv[4];
            ldsm_x4_t(tv, uV + r * 64 + ((ch ^ ((r >> 1) & 3)) * 16));
            uint32_t b0[2] = {tv[0], tv[1]}, b1[2] = {tv[2], tv[3]};
            mma_f16(o[ncp * 2],     ah, b0);
            mma_f16(o[ncp * 2],     al, b0);
            mma_f16(o[ncp * 2 + 1], ah, b1);
            mma_f16(o[ncp * 2 + 1], al, b1);
        }
    }

#pragma unroll
    for (int ng = 0; ng < 4; ng++) {
        int d = ng * 8 + q2 * 2;
        int col = h * 32 + d;
        size_t r0o = ((size_t)b * 144 + i0) * 384 + col;
        size_t r1o = ((size_t)b * 144 + i1) * 384 + col;
        __half h0 = __float2half_rn(o[ng][0]);
        __half h1 = __float2half_rn(o[ng][1]);
        __half h2 = __float2half_rn(o[ng][2]);
        __half h3 = __float2half_rn(o[ng][3]);
        *(uint32_t*)(g_att_hi + r0o) = pack_h2(h0, h1);
        *(uint32_t*)(g_att_hi + r1o) = pack_h2(h2, h3);
        *(uint32_t*)(g_att_lo + r0o) =
            pack_h2(__float2half_rn(o[ng][0] - __half2float(h0)),
                    __float2half_rn(o[ng][1] - __half2float(h1)));
        *(uint32_t*)(g_att_lo + r1o) =
            pack_h2(__float2half_rn(o[ng][2] - __half2float(h2)),
                    __float2half_rn(o[ng][3] - __half2float(h3)));
    }
}

// ---------------------------------------------------------------------------
extern "C" void kernel_launch(void* const* d_in, const int* in_sizes, int n_in,
                              void* d_out, int out_size)
{
    const float* x          = (const float*)d_in[0];
    const float* mask       = (const float*)d_in[1];
    const float* w_qkv      = (const float*)d_in[2];
    const float* b_qkv      = (const float*)d_in[3];
    const float* w_out      = (const float*)d_in[4];
    const float* b_out      = (const float*)d_in[5];
    const float* bias_table = (const float*)d_in[6];
    const int*   pos_idx    = (const int*)d_in[7];
    float* out = (float*)d_out;

    __half *xa_hi, *xa_lo, *wqT, *woT, *att_hi, *att_lo;
    cudaGetSymbolAddress((void**)&xa_hi, g_xa_hi);
    cudaGetSymbolAddress((void**)&xa_lo, g_xa_lo);
    cudaGetSymbolAddress((void**)&wqT, g_wqkvT);
    cudaGetSymbolAddress((void**)&woT, g_woutT);
    cudaGetSymbolAddress((void**)&att_hi, g_att_hi);
    cudaGetSymbolAddress((void**)&att_lo, g_att_lo);

    const int smem_gemm = 3 * STG32;  // 72 KB
    cudaFuncSetAttribute(hmma_gemm_kernel, cudaFuncAttributeMaxDynamicSharedMemorySize,
                         smem_gemm);
    const int smem_attn = 18432 + 9216 + 9216 + 2592 * 4;  // 47232
    cudaFuncSetAttribute(attn_mma_kernel, cudaFuncAttributeMaxDynamicSharedMemorySize,
                         smem_attn);

    convert_x_kernel<<<2048, 256>>>(x, xa_hi, xa_lo, MROWS * DIM / 4);
    convert_wT_kernel<<<(DIM * QKV_N + 255) / 256, 256>>>(w_qkv, wqT, DIM, QKV_N);
    convert_wT_kernel<<<(DIM * DIM + 255) / 256, 256>>>(w_out, woT, DIM, DIM);
    // qkv projection -> packed q/k/v
    hmma_gemm_kernel<<<dim3(QKV_N / 128, MROWS / 128), 256, smem_gemm>>>(
        xa_hi, xa_lo, wqT, b_qkv, nullptr, 0);
    // attention
    attn_mma_kernel<<<B_WIN * HEADS, 288, smem_attn>>>(mask, bias_table, pos_idx);
    // output projection
    hmma_gemm_kernel<<<dim3(DIM / 128, MROWS / 128), 256, smem_gemm>>>(
        att_hi, att_lo, woT, b_out, out, 1);
}

// round 11
// speedup vs baseline: 2.3866x; 1.8894x over previous
#include <cuda_runtime.h>
#include <cuda_fp16.h>
#include <cstdint>

// Problem constants
#define B_WIN 256
#define NTOK  144
#define DIM   384
#define HEADS 12
#define HD    32
#define QKV_N 1152
#define MROWS (B_WIN*NTOK)        // 36864
#define QSCALE 0.17677669529663689f   // 32^-0.5

// Packed planes inside g_qkvp (all single fp16, 64B rows, 4 chunks,
// swizzle phys = c ^ ((r>>1)&3)):
#define Q_OFF 0ll
#define K_OFF 28311552ll
#define V_OFF 56623104ll

// ---------------- Scratch (static device globals; allocation-free) ----------
__device__ char   g_qkvp[84934656];
__device__ __half g_xa[14155776];      // x fp16, [36864][384]
__device__ __half g_wqkvT[442368];     // [1152][384]
__device__ __half g_woutT[147456];     // [384][384]
__device__ __half g_att[14155776];     // attention out fp16, [36864][384]

// ---------------- helpers ---------------------------------------------------
__device__ __forceinline__ uint32_t smem_u32(const void* p) {
    return (uint32_t)__cvta_generic_to_shared(p);
}
__device__ __forceinline__ uint32_t pack_h2(__half a, __half b) {
    return (uint32_t)__half_as_ushort(a) | ((uint32_t)__half_as_ushort(b) << 16);
}
__device__ __forceinline__ void ldsm_x4(uint32_t* r, uint32_t addr) {
    asm volatile("ldmatrix.sync.aligned.m8n8.x4.shared.b16 {%0,%1,%2,%3}, [%4];"
                 : "=r"(r[0]), "=r"(r[1]), "=r"(r[2]), "=r"(r[3]) : "r"(addr));
}
__device__ __forceinline__ void ldsm_x4_t(uint32_t* r, uint32_t addr) {
    asm volatile("ldmatrix.sync.aligned.m8n8.x4.trans.shared.b16 {%0,%1,%2,%3}, [%4];"
                 : "=r"(r[0]), "=r"(r[1]), "=r"(r[2]), "=r"(r[3]) : "r"(addr));
}
__device__ __forceinline__ void mma_f16(float* c, const uint32_t* a, const uint32_t* b) {
    asm volatile(
        "mma.sync.aligned.m16n8k16.row.col.f32.f16.f16.f32 "
        "{%0,%1,%2,%3}, {%4,%5,%6,%7}, {%8,%9}, {%0,%1,%2,%3};"
        : "+f"(c[0]), "+f"(c[1]), "+f"(c[2]), "+f"(c[3])
        : "r"(a[0]), "r"(a[1]), "r"(a[2]), "r"(a[3]), "r"(b[0]), "r"(b[1]));
}
__device__ __forceinline__ void cp_async16(uint32_t s, const void* g) {
    asm volatile("cp.async.cg.shared.global [%0], [%1], 16;" :: "r"(s), "l"(g));
}
#define CP_COMMIT() asm volatile("cp.async.commit_group;" ::: "memory")
#define CP_WAIT1()  asm volatile("cp.async.wait_group 1;" ::: "memory")
#define CP_WAIT0()  asm volatile("cp.async.wait_group 0;" ::: "memory")

// ---------------------------------------------------------------------------
// Prep kernels
// ---------------------------------------------------------------------------
__global__ void convert_x_kernel(const float* __restrict__ x,
                                 __half* __restrict__ dst, int n4)
{
    int idx = blockIdx.x * blockDim.x + threadIdx.x;
    int stride = gridDim.x * blockDim.x;
    for (; idx < n4; idx += stride) {
        float4 v = ((const float4*)x)[idx];
        ((uint2*)dst)[idx] = make_uint2(
            pack_h2(__float2half_rn(v.x), __float2half_rn(v.y)),
            pack_h2(__float2half_rn(v.z), __float2half_rn(v.w)));
    }
}

__global__ void convert_wT_kernel(const float* __restrict__ w,
                                  __half* __restrict__ dst, int K, int Nn)
{
    int idx = blockIdx.x * blockDim.x + threadIdx.x;
    int total = K * Nn;
    if (idx >= total) return;
    int n = idx / K, k = idx - n * K;
    dst[idx] = __float2half_rn(w[(size_t)k * Nn + n]);
}

// ---------------------------------------------------------------------------
// HMMA fp16 GEMM, BK=32, 3-stage cp.async, 2 CTAs/SM.
// D(128x128) = A(128x384) @ B^T(128x384), fp32 accum.
// Tiles: A, B — 128 rows x 32 fp16 (64B row); swizzle phys = c ^ ((r>>1)&3).
// smem: 3 stages x 2 tiles x 8KB = 48KB.
// mode 0: qkv epilogue -> packed q/k/v planes (+bias, q-scale)
// mode 1: out epilogue (bias, write fp32 out)
// ---------------------------------------------------------------------------
#define TB32 8192
#define STG32 (2 * TB32)
#define NKC 12

__global__ __launch_bounds__(256, 2)
void hmma_gemm_kernel(const __half* __restrict__ Aa,
                      const __half* __restrict__ Bs,
                      const float* __restrict__ bias,
                      float* __restrict__ outp, int mode)
{
    extern __shared__ char smem[];
    const uint32_t usm = smem_u32(smem);

    const int tid = threadIdx.x;
    const int wid = tid >> 5, lane = tid & 31;
    const int bm = blockIdx.y * 128;
    const int bn = blockIdx.x * 128;
    const int wm = wid >> 2, wn = wid & 3;
    const int m0w = wm * 64, n0w = wn * 32;

    const int r0l = tid >> 2;            // rows 0..63 (iter 0), +64 (iter 1)
    const int c0l = tid & 3;

    float acc[4][4][4];
#pragma unroll
    for (int mt = 0; mt < 4; mt++)
#pragma unroll
        for (int nt = 0; nt < 4; nt++)
#pragma unroll
            for (int e = 0; e < 4; e++) acc[mt][nt][e] = 0.f;

    const int lr = lane & 15;
    const int lc = lane >> 4;

#define LOAD_STAGE32(kc, buf)                                                   \
    {                                                                           \
        uint32_t s0 = usm + (buf) * STG32;                                      \
        _Pragma("unroll")                                                       \
        for (int it = 0; it < 2; it++) {                                        \
            int r = r0l + it * 64;                                              \
            size_t gA = (size_t)(bm + r) * 384 + (kc) * 32 + c0l * 8;           \
            size_t gB = (size_t)(bn + r) * 384 + (kc) * 32 + c0l * 8;           \
            uint32_t d = r * 64 + ((c0l ^ ((r >> 1) & 3)) * 16);                \
            cp_async16(s0 + d, Aa + gA);                                        \
            cp_async16(s0 + TB32 + d, Bs + gB);                                 \
        }                                                                       \
        CP_COMMIT();                                                            \
    }

    LOAD_STAGE32(0, 0);
    LOAD_STAGE32(1, 1);

    int buf = 0;
    for (int kc = 0; kc < NKC; kc++) {
        if (kc < NKC - 1) { CP_WAIT1(); } else { CP_WAIT0(); }
        __syncthreads();
        if (kc + 2 < NKC) {
            int nb = buf + 2; if (nb >= 3) nb -= 3;
            LOAD_STAGE32(kc + 2, nb);
        }

        const uint32_t uA = usm + buf * STG32;
        const uint32_t uB = uA + TB32;

#pragma unroll
        for (int k16 = 0; k16 < 2; k16++) {
            const int chunk = k16 * 2 + lc;
            uint32_t aF[4][4];
            uint32_t bF[4][2];
#pragma unroll
            for (int mt = 0; mt < 4; mt++) {
                int r = m0w + mt * 16 + lr;
                uint32_t off = r * 64 + ((chunk ^ ((r >> 1) & 3)) * 16);
                ldsm_x4(aF[mt], uA + off);
            }
#pragma unroll
            for (int np = 0; np < 2; np++) {
                int r = n0w + np * 16 + lr;
                uint32_t off = r * 64 + ((chunk ^ ((r >> 1) & 3)) * 16);
                uint32_t t[4];
                ldsm_x4(t, uB + off);
                bF[2 * np][0] = t[0]; bF[2 * np][1] = t[2];
                bF[2 * np + 1][0] = t[1]; bF[2 * np + 1][1] = t[3];
            }
#pragma unroll
            for (int mt = 0; mt < 4; mt++)
#pragma unroll
                for (int nt = 0; nt < 4; nt++)
                    mma_f16(acc[mt][nt], aF[mt], bF[nt]);
        }
        __syncthreads();
        if (++buf == 3) buf = 0;
    }
#undef LOAD_STAGE32

    if (mode == 0) {
#pragma unroll
        for (int mt = 0; mt < 4; mt++) {
#pragma unroll
            for (int nt = 0; nt < 4; nt++) {
                int col = bn + n0w + nt * 8 + (lane & 3) * 2;
                int s = col / 384;
                int rem = col - s * 384;
                int hh = rem >> 5, d = rem & 31;
                float sc = (s == 0) ? QSCALE : 1.0f;
                float b0 = bias[col], b1 = bias[col + 1];
                char* plane = g_qkvp + ((s == 0) ? Q_OFF : (s == 1) ? K_OFF : V_OFF);
                int ch = d >> 3;
                int byt = (d & 7) * 2;
#pragma unroll
                for (int half2_ = 0; half2_ < 2; half2_++) {
                    int row = bm + m0w + mt * 16 + (lane >> 2) + half2_ * 8;
                    int b = row / 144, i = row - b * 144;
                    float v0 = (acc[mt][nt][half2_ * 2 + 0] + b0) * sc;
                    float v1 = (acc[mt][nt][half2_ * 2 + 1] + b1) * sc;
                    char* base = plane + ((size_t)(b * 12 + hh) * 144 + i) * 64;
                    *(uint32_t*)(base + ((ch ^ ((i >> 1) & 3)) * 16) + byt) =
                        pack_h2(__float2half_rn(v0), __float2half_rn(v1));
                }
            }
        }
    } else {
#pragma unroll
        for (int mt = 0; mt < 4; mt++) {
#pragma unroll
            for (int nt = 0; nt < 4; nt++) {
                int col = bn + n0w + nt * 8 + (lane & 3) * 2;
                float b0 = bias[col], b1 = bias[col + 1];
#pragma unroll
                for (int half2_ = 0; half2_ < 2; half2_++) {
                    int row = bm + m0w + mt * 16 + (lane >> 2) + half2_ * 8;
                    float2 v;
                    v.x = acc[mt][nt][half2_ * 2 + 0] + b0;
                    v.y = acc[mt][nt][half2_ * 2 + 1] + b1;
                    *(float2*)(outp + (size_t)row * 384 + col) = v;
                }
            }
        }
    }
}

// ---------------------------------------------------------------------------
// Flash-style HMMA attention, single fp16.
// Q/K/V all 64B-row fp16 planes. One block per (b,h), 9 warps.
// ---------------------------------------------------------------------------
__global__ __launch_bounds__(288, 2)
void attn_mma_kernel(const float* __restrict__ mask,
                     const float* __restrict__ bias_table,
                     const int*   __restrict__ pos_idx)
{
    extern __shared__ char sm[];
    char* sQ = sm;                     // 9216 B
    char* sK = sm + 9216;              // 9216 B
    char* sV = sm + 18432;             // 9216 B
    float* sB = (float*)(sm + 27648);  // 2592 floats
    const uint32_t uQ = smem_u32(sQ), uK = smem_u32(sK), uV = smem_u32(sV);

    const int bh = blockIdx.x;
    const int b = bh / HEADS, h = bh - b * HEADS;
    const int g  = b >> 5;
    const int t  = b & 31;
    const int mw = b & 7;

    const int tid = threadIdx.x;
    const int wid = tid >> 5, lane = tid & 31;

    {
        const uint4* q = (const uint4*)(g_qkvp + Q_OFF + (size_t)bh * 9216);
        const uint4* k = (const uint4*)(g_qkvp + K_OFF + (size_t)bh * 9216);
        const uint4* v = (const uint4*)(g_qkvp + V_OFF + (size_t)bh * 9216);
        uint4* dq = (uint4*)sQ; uint4* dk = (uint4*)sK; uint4* dv = (uint4*)sV;
        for (int i = tid; i < 576; i += 288) { dq[i] = q[i]; dk[i] = k[i]; dv[i] = v[i]; }
    }
    for (int s = tid; s < 2592; s += 288)
        sB[s] = bias_table[(size_t)pos_idx[8 * s + g] * (32 * HEADS) + t * HEADS + h];
    __syncthreads();

    const int m0 = wid * 16;
    const int gr = lane >> 2, q2 = lane & 3;
    const int i0 = m0 + gr, i1 = i0 + 8;

    float c[18][4];
    {
        const float* mrow0 = mask + ((size_t)mw * 144 + i0) * 144;
        const float* mrow1 = mask + ((size_t)mw * 144 + i1) * 144;
        const float* brow0 = sB + (i0 % 18) * 144;
        const float* brow1 = sB + (i1 % 18) * 144;
#pragma unroll
        for (int nt = 0; nt < 18; nt++) {
            int j = nt * 8 + q2 * 2;
            float2 mv0 = *(const float2*)(mrow0 + j);
            float2 mv1 = *(const float2*)(mrow1 + j);
            float2 bv0 = *(const float2*)(brow0 + j);
            float2 bv1 = *(const float2*)(brow1 + j);
            c[nt][0] = mv0.x + bv0.x; c[nt][1] = mv0.y + bv0.y;
            c[nt][2] = mv1.x + bv1.x; c[nt][3] = mv1.y + bv1.y;
        }
    }

    const int lr = lane & 15, lc = lane >> 4;
#pragma unroll
    for (int kk = 0; kk < 2; kk++) {
        uint32_t aF[4];
        {
            int r = m0 + lr;
            int ch = kk * 2 + lc;
            ldsm_x4(aF, uQ + r * 64 + ((ch ^ ((r >> 1) & 3)) * 16));
        }
#pragma unroll
        for (int np = 0; np < 9; np++) {
            int r = np * 16 + lr;
            int ch = kk * 2 + lc;
            uint32_t tK[4];
            ldsm_x4(tK, uK + r * 64 + ((ch ^ ((r >> 1) & 3)) * 16));
            uint32_t b0[2] = {tK[0], tK[2]}, b1[2] = {tK[1], tK[3]};
            mma_f16(c[2 * np],     aF, b0);
            mma_f16(c[2 * np + 1], aF, b1);
        }
    }

    float mx0 = -1e30f, mx1 = -1e30f;
#pragma unroll
    for (int nt = 0; nt < 18; nt++) {
        mx0 = fmaxf(mx0, fmaxf(c[nt][0], c[nt][1]));
        mx1 = fmaxf(mx1, fmaxf(c[nt][2], c[nt][3]));
    }
    mx0 = fmaxf(mx0, __shfl_xor_sync(0xffffffffu, mx0, 1));
    mx0 = fmaxf(mx0, __shfl_xor_sync(0xffffffffu, mx0, 2));
    mx1 = fmaxf(mx1, __shfl_xor_sync(0xffffffffu, mx1, 1));
    mx1 = fmaxf(mx1, __shfl_xor_sync(0xffffffffu, mx1, 2));
    float s0 = 0.f, s1 = 0.f;
#pragma unroll
    for (int nt = 0; nt < 18; nt++) {
        c[nt][0] = __expf(c[nt][0] - mx0); s0 += c[nt][0];
        c[nt][1] = __expf(c[nt][1] - mx0); s0 += c[nt][1];
        c[nt][2] = __expf(c[nt][2] - mx1); s1 += c[nt][2];
        c[nt][3] = __expf(c[nt][3] - mx1); s1 += c[nt][3];
    }
    s0 += __shfl_xor_sync(0xffffffffu, s0, 1);
    s0 += __shfl_xor_sync(0xffffffffu, s0, 2);
    s1 += __shfl_xor_sync(0xffffffffu, s1, 1);
    s1 += __shfl_xor_sync(0xffffffffu, s1, 2);
    float inv0 = 1.f / s0, inv1 = 1.f / s1;
#pragma unroll
    for (int nt = 0; nt < 18; nt++) {
        c[nt][0] *= inv0; c[nt][1] *= inv0;
        c[nt][2] *= inv1; c[nt][3] *= inv1;
    }

    float o[4][4];
#pragma unroll
    for (int ng = 0; ng < 4; ng++)
#pragma unroll
        for (int e = 0; e < 4; e++) o[ng][e] = 0.f;

    const int grp = lane >> 3, wi = lane & 7;
#pragma unroll
    for (int kk = 0; kk < 9; kk++) {
        uint32_t ah[4];
#pragma unroll
        for (int p = 0; p < 4; p++) {
            const float x = c[(p < 2) ? 2 * kk : 2 * kk + 1][(p & 1) * 2 + 0];
            const float y = c[(p < 2) ? 2 * kk : 2 * kk + 1][(p & 1) * 2 + 1];
            ah[p] = pack_h2(__float2half_rn(x), __float2half_rn(y));
        }
        int r = kk * 16 + (grp & 1) * 8 + wi;
#pragma unroll
        for (int ncp = 0; ncp < 2; ncp++) {
            int ch = ncp * 2 + (grp >> 1);
            uint32_t tv[4];
            ldsm_x4_t(tv, uV + r * 64 + ((ch ^ ((r >> 1) & 3)) * 16));
            uint32_t b0[2] = {tv[0], tv[1]}, b1[2] = {tv[2], tv[3]};
            mma_f16(o[ncp * 2],     ah, b0);
            mma_f16(o[ncp * 2 + 1], ah, b1);
        }
    }

#pragma unroll
    for (int ng = 0; ng < 4; ng++) {
        int d = ng * 8 + q2 * 2;
        int col = h * 32 + d;
        size_t r0o = ((size_t)b * 144 + i0) * 384 + col;
        size_t r1o = ((size_t)b * 144 + i1) * 384 + col;
        *(uint32_t*)(g_att + r0o) =
            pack_h2(__float2half_rn(o[ng][0]), __float2half_rn(o[ng][1]));
        *(uint32_t*)(g_att + r1o) =
            pack_h2(__float2half_rn(o[ng][2]), __float2half_rn(o[ng][3]));
    }
}

// ---------------------------------------------------------------------------
extern "C" void kernel_launch(void* const* d_in, const int* in_sizes, int n_in,
                              void* d_out, int out_size)
{
    const float* x          = (const float*)d_in[0];
    const float* mask       = (const float*)d_in[1];
    const float* w_qkv      = (const float*)d_in[2];
    const float* b_qkv      = (const float*)d_in[3];
    const float* w_out      = (const float*)d_in[4];
    const float* b_out      = (const float*)d_in[5];
    const float* bias_table = (const float*)d_in[6];
    const int*   pos_idx    = (const int*)d_in[7];
    float* out = (float*)d_out;

    __half *xa, *wqT, *woT, *att;
    cudaGetSymbolAddress((void**)&xa, g_xa);
    cudaGetSymbolAddress((void**)&wqT, g_wqkvT);
    cudaGetSymbolAddress((void**)&woT, g_woutT);
    cudaGetSymbolAddress((void**)&att, g_att);

    const int smem_gemm = 3 * STG32;  // 48 KB
    cudaFuncSetAttribute(hmma_gemm_kernel, cudaFuncAttributeMaxDynamicSharedMemorySize,
                         smem_gemm);
    const int smem_attn = 3 * 9216 + 2592 * 4;  // 38016
    cudaFuncSetAttribute(attn_mma_kernel, cudaFuncAttributeMaxDynamicSharedMemorySize,
                         smem_attn);

    convert_x_kernel<<<2048, 256>>>(x, xa, MROWS * DIM / 4);
    convert_wT_kernel<<<(DIM * QKV_N + 255) / 256, 256>>>(w_qkv, wqT, DIM, QKV_N);
    convert_wT_kernel<<<(DIM * DIM + 255) / 256, 256>>>(w_out, woT, DIM, DIM);
    // qkv projection -> packed q/k/v
    hmma_gemm_kernel<<<dim3(QKV_N / 128, MROWS / 128), 256, smem_gemm>>>(
        xa, wqT, b_qkv, nullptr, 0);
    // attention
    attn_mma_kernel<<<B_WIN * HEADS, 288, smem_attn>>>(mask, bias_table, pos_idx);
    // output projection
    hmma_gemm_kernel<<<dim3(DIM / 128, MROWS / 128), 256, smem_gemm>>>(
        att, woT, b_out, out, 1);
}

// round 12
// speedup vs baseline: 2.4899x; 1.0433x over previous
#include <cuda_runtime.h>
#include <cuda_fp16.h>
#include <cstdint>

// Problem constants
#define B_WIN 256
#define NTOK  144
#define DIM   384
#define HEADS 12
#define HD    32
#define QKV_N 1152
#define MROWS (B_WIN*NTOK)        // 36864
#define QSCALE 0.17677669529663689f   // 32^-0.5

// Packed planes inside g_qkvp (all single fp16, 64B rows, 4 chunks,
// swizzle phys = c ^ ((r>>1)&3)):
#define Q_OFF 0ll
#define K_OFF 28311552ll
#define V_OFF 56623104ll

// ---------------- Scratch (static device globals; allocation-free) ----------
__device__ char   g_qkvp[84934656];
__device__ __half g_xa[14155776];      // x fp16, [36864][384]
__device__ __half g_wqkvT[442368];     // [1152][384]
__device__ __half g_woutT[147456];     // [384][384]
__device__ __half g_att[14155776];     // attention out fp16, [36864][384]

// ---------------- helpers ---------------------------------------------------
__device__ __forceinline__ uint32_t smem_u32(const void* p) {
    return (uint32_t)__cvta_generic_to_shared(p);
}
__device__ __forceinline__ uint32_t pack_h2(__half a, __half b) {
    return (uint32_t)__half_as_ushort(a) | ((uint32_t)__half_as_ushort(b) << 16);
}
__device__ __forceinline__ void ldsm_x4(uint32_t* r, uint32_t addr) {
    asm volatile("ldmatrix.sync.aligned.m8n8.x4.shared.b16 {%0,%1,%2,%3}, [%4];"
                 : "=r"(r[0]), "=r"(r[1]), "=r"(r[2]), "=r"(r[3]) : "r"(addr));
}
__device__ __forceinline__ void ldsm_x4_t(uint32_t* r, uint32_t addr) {
    asm volatile("ldmatrix.sync.aligned.m8n8.x4.trans.shared.b16 {%0,%1,%2,%3}, [%4];"
                 : "=r"(r[0]), "=r"(r[1]), "=r"(r[2]), "=r"(r[3]) : "r"(addr));
}
__device__ __forceinline__ void mma_f16(float* c, const uint32_t* a, const uint32_t* b) {
    asm volatile(
        "mma.sync.aligned.m16n8k16.row.col.f32.f16.f16.f32 "
        "{%0,%1,%2,%3}, {%4,%5,%6,%7}, {%8,%9}, {%0,%1,%2,%3};"
        : "+f"(c[0]), "+f"(c[1]), "+f"(c[2]), "+f"(c[3])
        : "r"(a[0]), "r"(a[1]), "r"(a[2]), "r"(a[3]), "r"(b[0]), "r"(b[1]));
}
__device__ __forceinline__ void cp_async16(uint32_t s, const void* g) {
    asm volatile("cp.async.cg.shared.global [%0], [%1], 16;" :: "r"(s), "l"(g));
}
#define CP_COMMIT() asm volatile("cp.async.commit_group;" ::: "memory")
#define CP_WAIT1()  asm volatile("cp.async.wait_group 1;" ::: "memory")
#define CP_WAIT0()  asm volatile("cp.async.wait_group 0;" ::: "memory")

// ---------------------------------------------------------------------------
// Prep kernels
// ---------------------------------------------------------------------------
__global__ void convert_x_kernel(const float* __restrict__ x,
                                 __half* __restrict__ dst, int n4)
{
    int idx = blockIdx.x * blockDim.x + threadIdx.x;
    int stride = gridDim.x * blockDim.x;
    for (; idx < n4; idx += stride) {
        float4 v = ((const float4*)x)[idx];
        ((uint2*)dst)[idx] = make_uint2(
            pack_h2(__float2half_rn(v.x), __float2half_rn(v.y)),
            pack_h2(__float2half_rn(v.z), __float2half_rn(v.w)));
    }
}

__global__ void convert_wT_kernel(const float* __restrict__ w,
                                  __half* __restrict__ dst, int K, int Nn)
{
    int idx = blockIdx.x * blockDim.x + threadIdx.x;
    int total = K * Nn;
    if (idx >= total) return;
    int n = idx / K, k = idx - n * K;
    dst[idx] = __float2half_rn(w[(size_t)k * Nn + n]);
}

// ---------------------------------------------------------------------------
// HMMA fp16 GEMM, BK=32, 3-stage cp.async, 2 CTAs/SM. (unchanged from R11)
// ---------------------------------------------------------------------------
#define TB32 8192
#define STG32 (2 * TB32)
#define NKC 12

__global__ __launch_bounds__(256, 2)
void hmma_gemm_kernel(const __half* __restrict__ Aa,
                      const __half* __restrict__ Bs,
                      const float* __restrict__ bias,
                      float* __restrict__ outp, int mode)
{
    extern __shared__ char smem[];
    const uint32_t usm = smem_u32(smem);

    const int tid = threadIdx.x;
    const int wid = tid >> 5, lane = tid & 31;
    const int bm = blockIdx.y * 128;
    const int bn = blockIdx.x * 128;
    const int wm = wid >> 2, wn = wid & 3;
    const int m0w = wm * 64, n0w = wn * 32;

    const int r0l = tid >> 2;
    const int c0l = tid & 3;

    float acc[4][4][4];
#pragma unroll
    for (int mt = 0; mt < 4; mt++)
#pragma unroll
        for (int nt = 0; nt < 4; nt++)
#pragma unroll
            for (int e = 0; e < 4; e++) acc[mt][nt][e] = 0.f;

    const int lr = lane & 15;
    const int lc = lane >> 4;

#define LOAD_STAGE32(kc, buf)                                                   \
    {                                                                           \
        uint32_t s0 = usm + (buf) * STG32;                                      \
        _Pragma("unroll")                                                       \
        for (int it = 0; it < 2; it++) {                                        \
            int r = r0l + it * 64;                                              \
            size_t gA = (size_t)(bm + r) * 384 + (kc) * 32 + c0l * 8;           \
            size_t gB = (size_t)(bn + r) * 384 + (kc) * 32 + c0l * 8;           \
            uint32_t d = r * 64 + ((c0l ^ ((r >> 1) & 3)) * 16);                \
            cp_async16(s0 + d, Aa + gA);                                        \
            cp_async16(s0 + TB32 + d, Bs + gB);                                 \
        }                                                                       \
        CP_COMMIT();                                                            \
    }

    LOAD_STAGE32(0, 0);
    LOAD_STAGE32(1, 1);

    int buf = 0;
    for (int kc = 0; kc < NKC; kc++) {
        if (kc < NKC - 1) { CP_WAIT1(); } else { CP_WAIT0(); }
        __syncthreads();
        if (kc + 2 < NKC) {
            int nb = buf + 2; if (nb >= 3) nb -= 3;
            LOAD_STAGE32(kc + 2, nb);
        }

        const uint32_t uA = usm + buf * STG32;
        const uint32_t uB = uA + TB32;

#pragma unroll
        for (int k16 = 0; k16 < 2; k16++) {
            const int chunk = k16 * 2 + lc;
            uint32_t aF[4][4];
            uint32_t bF[4][2];
#pragma unroll
            for (int mt = 0; mt < 4; mt++) {
                int r = m0w + mt * 16 + lr;
                uint32_t off = r * 64 + ((chunk ^ ((r >> 1) & 3)) * 16);
                ldsm_x4(aF[mt], uA + off);
            }
#pragma unroll
            for (int np = 0; np < 2; np++) {
                int r = n0w + np * 16 + lr;
                uint32_t off = r * 64 + ((chunk ^ ((r >> 1) & 3)) * 16);
                uint32_t t[4];
                ldsm_x4(t, uB + off);
                bF[2 * np][0] = t[0]; bF[2 * np][1] = t[2];
                bF[2 * np + 1][0] = t[1]; bF[2 * np + 1][1] = t[3];
            }
#pragma unroll
            for (int mt = 0; mt < 4; mt++)
#pragma unroll
                for (int nt = 0; nt < 4; nt++)
                    mma_f16(acc[mt][nt], aF[mt], bF[nt]);
        }
        __syncthreads();
        if (++buf == 3) buf = 0;
    }
#undef LOAD_STAGE32

    if (mode == 0) {
#pragma unroll
        for (int mt = 0; mt < 4; mt++) {
#pragma unroll
            for (int nt = 0; nt < 4; nt++) {
                int col = bn + n0w + nt * 8 + (lane & 3) * 2;
                int s = col / 384;
                int rem = col - s * 384;
                int hh = rem >> 5, d = rem & 31;
                float sc = (s == 0) ? QSCALE : 1.0f;
                float b0 = bias[col], b1 = bias[col + 1];
                char* plane = g_qkvp + ((s == 0) ? Q_OFF : (s == 1) ? K_OFF : V_OFF);
                int ch = d >> 3;
                int byt = (d & 7) * 2;
#pragma unroll
                for (int half2_ = 0; half2_ < 2; half2_++) {
                    int row = bm + m0w + mt * 16 + (lane >> 2) + half2_ * 8;
                    int b = row / 144, i = row - b * 144;
                    float v0 = (acc[mt][nt][half2_ * 2 + 0] + b0) * sc;
                    float v1 = (acc[mt][nt][half2_ * 2 + 1] + b1) * sc;
                    char* base = plane + ((size_t)(b * 12 + hh) * 144 + i) * 64;
                    *(uint32_t*)(base + ((ch ^ ((i >> 1) & 3)) * 16) + byt) =
                        pack_h2(__float2half_rn(v0), __float2half_rn(v1));
                }
            }
        }
    } else {
#pragma unroll
        for (int mt = 0; mt < 4; mt++) {
#pragma unroll
            for (int nt = 0; nt < 4; nt++) {
                int col = bn + n0w + nt * 8 + (lane & 3) * 2;
                float b0 = bias[col], b1 = bias[col + 1];
#pragma unroll
                for (int half2_ = 0; half2_ < 2; half2_++) {
                    int row = bm + m0w + mt * 16 + (lane >> 2) + half2_ * 8;
                    float2 v;
                    v.x = acc[mt][nt][half2_ * 2 + 0] + b0;
                    v.y = acc[mt][nt][half2_ * 2 + 1] + b1;
                    *(float2*)(outp + (size_t)row * 384 + col) = v;
                }
            }
        }
    }
}

// ---------------------------------------------------------------------------
// Flash-style HMMA attention, single fp16.
// R12: bias gather held in regs & overlapped with QK (zero-init C, add after);
//      P pre-converted to fp16 post-softmax (c[] dies before PV);
//      QKV tile copy via cp.async.
// ---------------------------------------------------------------------------
__global__ __launch_bounds__(288, 2)
void attn_mma_kernel(const float* __restrict__ mask,
                     const float* __restrict__ bias_table,
                     const int*   __restrict__ pos_idx)
{
    extern __shared__ char sm[];
    char* sQ = sm;                     // 9216 B
    char* sK = sm + 9216;              // 9216 B
    char* sV = sm + 18432;             // 9216 B
    float* sB = (float*)(sm + 27648);  // 2592 floats
    const uint32_t uQ = smem_u32(sQ), uK = smem_u32(sK), uV = smem_u32(sV);

    const int bh = blockIdx.x;
    const int b = bh / HEADS, h = bh - b * HEADS;
    const int g  = b >> 5;
    const int t  = b & 31;
    const int mw = b & 7;

    const int tid = threadIdx.x;
    const int wid = tid >> 5, lane = tid & 31;

    // 1. QKV tile copy via cp.async (6 lines/thread)
    {
        const char* q = g_qkvp + Q_OFF + (size_t)bh * 9216;
        const char* k = g_qkvp + K_OFF + (size_t)bh * 9216;
        const char* v = g_qkvp + V_OFF + (size_t)bh * 9216;
#pragma unroll
        for (int it = 0; it < 2; it++) {
            int i = tid + it * 288;
            cp_async16(uQ + i * 16, q + i * 16);
            cp_async16(uK + i * 16, k + i * 16);
            cp_async16(uV + i * 16, v + i * 16);
        }
        CP_COMMIT();
    }

    // 2. bias gather into registers (latency overlapped with QK below)
    float bv[9];
#pragma unroll
    for (int kq = 0; kq < 9; kq++) {
        int s = tid + kq * 288;
        bv[kq] = bias_table[(size_t)pos_idx[8 * s + g] * (32 * HEADS) + t * HEADS + h];
    }

    CP_WAIT0();
    __syncthreads();

    const int m0 = wid * 16;
    const int gr = lane >> 2, q2 = lane & 3;
    const int i0 = m0 + gr, i1 = i0 + 8;

    // 3. QK^T with zero-initialized C
    float c[18][4];
#pragma unroll
    for (int nt = 0; nt < 18; nt++)
#pragma unroll
        for (int e = 0; e < 4; e++) c[nt][e] = 0.f;

    const int lr = lane & 15, lc = lane >> 4;
#pragma unroll
    for (int kk = 0; kk < 2; kk++) {
        uint32_t aF[4];
        {
            int r = m0 + lr;
            int ch = kk * 2 + lc;
            ldsm_x4(aF, uQ + r * 64 + ((ch ^ ((r >> 1) & 3)) * 16));
        }
#pragma unroll
        for (int np = 0; np < 9; np++) {
            int r = np * 16 + lr;
            int ch = kk * 2 + lc;
            uint32_t tK[4];
            ldsm_x4(tK, uK + r * 64 + ((ch ^ ((r >> 1) & 3)) * 16));
            uint32_t b0[2] = {tK[0], tK[2]}, b1[2] = {tK[1], tK[3]};
            mma_f16(c[2 * np],     aF, b0);
            mma_f16(c[2 * np + 1], aF, b1);
        }
    }

    // 4. publish gathered bias, then add bias + mask
#pragma unroll
    for (int kq = 0; kq < 9; kq++) sB[tid + kq * 288] = bv[kq];
    __syncthreads();
    {
        const float* mrow0 = mask + ((size_t)mw * 144 + i0) * 144;
        const float* mrow1 = mask + ((size_t)mw * 144 + i1) * 144;
        const float* brow0 = sB + (i0 % 18) * 144;
        const float* brow1 = sB + (i1 % 18) * 144;
#pragma unroll
        for (int nt = 0; nt < 18; nt++) {
            int j = nt * 8 + q2 * 2;
            float2 mv0 = *(const float2*)(mrow0 + j);
            float2 mv1 = *(const float2*)(mrow1 + j);
            float2 bv0 = *(const float2*)(brow0 + j);
            float2 bv1 = *(const float2*)(brow1 + j);
            c[nt][0] += mv0.x + bv0.x; c[nt][1] += mv0.y + bv0.y;
            c[nt][2] += mv1.x + bv1.x; c[nt][3] += mv1.y + bv1.y;
        }
    }

    // 5. in-register softmax
    float mx0 = -1e30f, mx1 = -1e30f;
#pragma unroll
    for (int nt = 0; nt < 18; nt++) {
        mx0 = fmaxf(mx0, fmaxf(c[nt][0], c[nt][1]));
        mx1 = fmaxf(mx1, fmaxf(c[nt][2], c[nt][3]));
    }
    mx0 = fmaxf(mx0, __shfl_xor_sync(0xffffffffu, mx0, 1));
    mx0 = fmaxf(mx0, __shfl_xor_sync(0xffffffffu, mx0, 2));
    mx1 = fmaxf(mx1, __shfl_xor_sync(0xffffffffu, mx1, 1));
    mx1 = fmaxf(mx1, __shfl_xor_sync(0xffffffffu, mx1, 2));
    float s0 = 0.f, s1 = 0.f;
#pragma unroll
    for (int nt = 0; nt < 18; nt++) {
        c[nt][0] = __expf(c[nt][0] - mx0); s0 += c[nt][0];
        c[nt][1] = __expf(c[nt][1] - mx0); s0 += c[nt][1];
        c[nt][2] = __expf(c[nt][2] - mx1); s1 += c[nt][2];
        c[nt][3] = __expf(c[nt][3] - mx1); s1 += c[nt][3];
    }
    s0 += __shfl_xor_sync(0xffffffffu, s0, 1);
    s0 += __shfl_xor_sync(0xffffffffu, s0, 2);
    s1 += __shfl_xor_sync(0xffffffffu, s1, 1);
    s1 += __shfl_xor_sync(0xffffffffu, s1, 2);
    float inv0 = 1.f / s0, inv1 = 1.f / s1;

    // 6. pre-convert P to packed fp16 A-frags; c[] dies here
    uint32_t ph[36];
#pragma unroll
    for (int kk = 0; kk < 9; kk++) {
#pragma unroll
        for (int p = 0; p < 4; p++) {
            int nt = (p < 2) ? 2 * kk : 2 * kk + 1;
            float sc0 = (p & 1) ? inv1 : inv0;
            float x = c[nt][(p & 1) * 2 + 0] * sc0;
            float y = c[nt][(p & 1) * 2 + 1] * sc0;
            ph[kk * 4 + p] = pack_h2(__float2half_rn(x), __float2half_rn(y));
        }
    }

    // 7. PV
    float o[4][4];
#pragma unroll
    for (int ng = 0; ng < 4; ng++)
#pragma unroll
        for (int e = 0; e < 4; e++) o[ng][e] = 0.f;

    const int grp = lane >> 3, wi = lane & 7;
#pragma unroll
    for (int kk = 0; kk < 9; kk++) {
        int r = kk * 16 + (grp & 1) * 8 + wi;
#pragma unroll
        for (int ncp = 0; ncp < 2; ncp++) {
            int ch = ncp * 2 + (grp >> 1);
            uint32_t tv[4];
            ldsm_x4_t(tv, uV + r * 64 + ((ch ^ ((r >> 1) & 3)) * 16));
            uint32_t b0[2] = {tv[0], tv[1]}, b1[2] = {tv[2], tv[3]};
            mma_f16(o[ncp * 2],     ph + kk * 4, b0);
            mma_f16(o[ncp * 2 + 1], ph + kk * 4, b1);
        }
    }

    // 8. store fp16 att rows
#pragma unroll
    for (int ng = 0; ng < 4; ng++) {
        int d = ng * 8 + q2 * 2;
        int col = h * 32 + d;
        size_t r0o = ((size_t)b * 144 + i0) * 384 + col;
        size_t r1o = ((size_t)b * 144 + i1) * 384 + col;
        *(uint32_t*)(g_att + r0o) =
            pack_h2(__float2half_rn(o[ng][0]), __float2half_rn(o[ng][1]));
        *(uint32_t*)(g_att + r1o) =
            pack_h2(__float2half_rn(o[ng][2]), __float2half_rn(o[ng][3]));
    }
}

// ---------------------------------------------------------------------------
extern "C" void kernel_launch(void* const* d_in, const int* in_sizes, int n_in,
                              void* d_out, int out_size)
{
    const float* x          = (const float*)d_in[0];
    const float* mask       = (const float*)d_in[1];
    const float* w_qkv      = (const float*)d_in[2];
    const float* b_qkv      = (const float*)d_in[3];
    const float* w_out      = (const float*)d_in[4];
    const float* b_out      = (const float*)d_in[5];
    const float* bias_table = (const float*)d_in[6];
    const int*   pos_idx    = (const int*)d_in[7];
    float* out = (float*)d_out;

    __half *xa, *wqT, *woT, *att;
    cudaGetSymbolAddress((void**)&xa, g_xa);
    cudaGetSymbolAddress((void**)&wqT, g_wqkvT);
    cudaGetSymbolAddress((void**)&woT, g_woutT);
    cudaGetSymbolAddress((void**)&att, g_att);

    const int smem_gemm = 3 * STG32;  // 48 KB
    cudaFuncSetAttribute(hmma_gemm_kernel, cudaFuncAttributeMaxDynamicSharedMemorySize,
                         smem_gemm);
    const int smem_attn = 3 * 9216 + 2592 * 4;  // 38016
    cudaFuncSetAttribute(attn_mma_kernel, cudaFuncAttributeMaxDynamicSharedMemorySize,
                         smem_attn);

    convert_x_kernel<<<2048, 256>>>(x, xa, MROWS * DIM / 4);
    convert_wT_kernel<<<(DIM * QKV_N + 255) / 256, 256>>>(w_qkv, wqT, DIM, QKV_N);
    convert_wT_kernel<<<(DIM * DIM + 255) / 256, 256>>>(w_out, woT, DIM, DIM);
    // qkv projection -> packed q/k/v
    hmma_gemm_kernel<<<dim3(QKV_N / 128, MROWS / 128), 256, smem_gemm>>>(
        xa, wqT, b_qkv, nullptr, 0);
    // attention
    attn_mma_kernel<<<B_WIN * HEADS, 288, smem_attn>>>(mask, bias_table, pos_idx);
    // output projection
    hmma_gemm_kernel<<<dim3(DIM / 128, MROWS / 128), 256, smem_gemm>>>(
        att, woT, b_out, out, 1);
}

// round 13
// speedup vs baseline: 2.6847x; 1.0782x over previous
#include <cuda_runtime.h>
#include <cuda_fp16.h>
#include <cstdint>

// Problem constants
#define B_WIN 256
#define NTOK  144
#define DIM   384
#define HEADS 12
#define HD    32
#define QKV_N 1152
#define MROWS (B_WIN*NTOK)        // 36864
#define QSCALE 0.17677669529663689f   // 32^-0.5
#define LOG2E  1.4426950408889634f
#define QSCL2E (QSCALE * LOG2E)

// Packed planes inside g_qkvp (all single fp16, 64B rows, 4 chunks,
// swizzle phys = c ^ ((r>>1)&3)):
#define Q_OFF 0ll
#define K_OFF 28311552ll
#define V_OFF 56623104ll

// ---------------- Scratch (static device globals; allocation-free) ----------
__device__ char   g_qkvp[84934656];
__device__ __half g_xa[14155776];      // x fp16, [36864][384]
__device__ __half g_wqkvT[442368];     // [1152][384]
__device__ __half g_woutT[147456];     // [384][384]
__device__ __half g_att[14155776];     // attention out fp16, [36864][384]
__device__ float  g_maskl[165888];     // mask * log2e, [8][144][144]

// ---------------- helpers ---------------------------------------------------
__device__ __forceinline__ uint32_t smem_u32(const void* p) {
    return (uint32_t)__cvta_generic_to_shared(p);
}
__device__ __forceinline__ uint32_t pack_h2(__half a, __half b) {
    return (uint32_t)__half_as_ushort(a) | ((uint32_t)__half_as_ushort(b) << 16);
}
__device__ __forceinline__ uint32_t packf2(float x, float y) {
    __half2 h = __float22half2_rn(make_float2(x, y));
    return *(uint32_t*)&h;
}
__device__ __forceinline__ float ex2(float x) {
    float y;
    asm("ex2.approx.ftz.f32 %0, %1;" : "=f"(y) : "f"(x));
    return y;
}
__device__ __forceinline__ void ldsm_x4(uint32_t* r, uint32_t addr) {
    asm volatile("ldmatrix.sync.aligned.m8n8.x4.shared.b16 {%0,%1,%2,%3}, [%4];"
                 : "=r"(r[0]), "=r"(r[1]), "=r"(r[2]), "=r"(r[3]) : "r"(addr));
}
__device__ __forceinline__ void ldsm_x4_t(uint32_t* r, uint32_t addr) {
    asm volatile("ldmatrix.sync.aligned.m8n8.x4.trans.shared.b16 {%0,%1,%2,%3}, [%4];"
                 : "=r"(r[0]), "=r"(r[1]), "=r"(r[2]), "=r"(r[3]) : "r"(addr));
}
__device__ __forceinline__ void mma_f16(float* c, const uint32_t* a, const uint32_t* b) {
    asm volatile(
        "mma.sync.aligned.m16n8k16.row.col.f32.f16.f16.f32 "
        "{%0,%1,%2,%3}, {%4,%5,%6,%7}, {%8,%9}, {%0,%1,%2,%3};"
        : "+f"(c[0]), "+f"(c[1]), "+f"(c[2]), "+f"(c[3])
        : "r"(a[0]), "r"(a[1]), "r"(a[2]), "r"(a[3]), "r"(b[0]), "r"(b[1]));
}
__device__ __forceinline__ void cp_async16(uint32_t s, const void* g) {
    asm volatile("cp.async.cg.shared.global [%0], [%1], 16;" :: "r"(s), "l"(g));
}
#define CP_COMMIT() asm volatile("cp.async.commit_group;" ::: "memory")
#define CP_WAIT1()  asm volatile("cp.async.wait_group 1;" ::: "memory")
#define CP_WAIT0()  asm volatile("cp.async.wait_group 0;" ::: "memory")

// ---------------------------------------------------------------------------
// Fused prep: x fp32->fp16, w_qkv/w_out transpose+convert, mask*log2e
// ---------------------------------------------------------------------------
__global__ void prep_kernel(const float* __restrict__ x,
                            const float* __restrict__ w_qkv,
                            const float* __restrict__ w_out,
                            const float* __restrict__ mask,
                            __half* __restrict__ xa,
                            __half* __restrict__ wqT,
                            __half* __restrict__ woT,
                            float* __restrict__ maskl)
{
    const int tid0 = blockIdx.x * blockDim.x + threadIdx.x;
    const int stride = gridDim.x * blockDim.x;
    // x: 3538944 float4 groups
    for (int idx = tid0; idx < MROWS * DIM / 4; idx += stride) {
        float4 v = ((const float4*)x)[idx];
        ((uint2*)xa)[idx] = make_uint2(packf2(v.x, v.y), packf2(v.z, v.w));
    }
    // w_qkv transpose: [384][1152] -> [1152][384]
    for (int idx = tid0; idx < DIM * QKV_N; idx += stride) {
        int n = idx / DIM, k = idx - n * DIM;
        wqT[idx] = __float2half_rn(w_qkv[(size_t)k * QKV_N + n]);
    }
    // w_out transpose: [384][384] -> [384][384]
    for (int idx = tid0; idx < DIM * DIM; idx += stride) {
        int n = idx / DIM, k = idx - n * DIM;
        woT[idx] = __float2half_rn(w_out[(size_t)k * DIM + n]);
    }
    // mask * log2e
    for (int idx = tid0; idx < 8 * NTOK * NTOK; idx += stride)
        maskl[idx] = mask[idx] * LOG2E;
}

// ---------------------------------------------------------------------------
// HMMA fp16 GEMM, BK=32, 3-stage cp.async, 2 CTAs/SM. (q scaled by QSCALE*log2e)
// ---------------------------------------------------------------------------
#define TB32 8192
#define STG32 (2 * TB32)
#define NKC 12

__global__ __launch_bounds__(256, 2)
void hmma_gemm_kernel(const __half* __restrict__ Aa,
                      const __half* __restrict__ Bs,
                      const float* __restrict__ bias,
                      float* __restrict__ outp, int mode)
{
    extern __shared__ char smem[];
    const uint32_t usm = smem_u32(smem);

    const int tid = threadIdx.x;
    const int wid = tid >> 5, lane = tid & 31;
    const int bm = blockIdx.y * 128;
    const int bn = blockIdx.x * 128;
    const int wm = wid >> 2, wn = wid & 3;
    const int m0w = wm * 64, n0w = wn * 32;

    const int r0l = tid >> 2;
    const int c0l = tid & 3;

    float acc[4][4][4];
#pragma unroll
    for (int mt = 0; mt < 4; mt++)
#pragma unroll
        for (int nt = 0; nt < 4; nt++)
#pragma unroll
            for (int e = 0; e < 4; e++) acc[mt][nt][e] = 0.f;

    const int lr = lane & 15;
    const int lc = lane >> 4;

#define LOAD_STAGE32(kc, buf)                                                   \
    {                                                                           \
        uint32_t s0 = usm + (buf) * STG32;                                      \
        _Pragma("unroll")                                                       \
        for (int it = 0; it < 2; it++) {                                        \
            int r = r0l + it * 64;                                              \
            size_t gA = (size_t)(bm + r) * 384 + (kc) * 32 + c0l * 8;           \
            size_t gB = (size_t)(bn + r) * 384 + (kc) * 32 + c0l * 8;           \
            uint32_t d = r * 64 + ((c0l ^ ((r >> 1) & 3)) * 16);                \
            cp_async16(s0 + d, Aa + gA);                                        \
            cp_async16(s0 + TB32 + d, Bs + gB);                                 \
        }                                                                       \
        CP_COMMIT();                                                            \
    }

    LOAD_STAGE32(0, 0);
    LOAD_STAGE32(1, 1);

    int buf = 0;
    for (int kc = 0; kc < NKC; kc++) {
        if (kc < NKC - 1) { CP_WAIT1(); } else { CP_WAIT0(); }
        __syncthreads();
        if (kc + 2 < NKC) {
            int nb = buf + 2; if (nb >= 3) nb -= 3;
            LOAD_STAGE32(kc + 2, nb);
        }

        const uint32_t uA = usm + buf * STG32;
        const uint32_t uB = uA + TB32;

#pragma unroll
        for (int k16 = 0; k16 < 2; k16++) {
            const int chunk = k16 * 2 + lc;
            uint32_t aF[4][4];
            uint32_t bF[4][2];
#pragma unroll
            for (int mt = 0; mt < 4; mt++) {
                int r = m0w + mt * 16 + lr;
                uint32_t off = r * 64 + ((chunk ^ ((r >> 1) & 3)) * 16);
                ldsm_x4(aF[mt], uA + off);
            }
#pragma unroll
            for (int np = 0; np < 2; np++) {
                int r = n0w + np * 16 + lr;
                uint32_t off = r * 64 + ((chunk ^ ((r >> 1) & 3)) * 16);
                uint32_t t[4];
                ldsm_x4(t, uB + off);
                bF[2 * np][0] = t[0]; bF[2 * np][1] = t[2];
                bF[2 * np + 1][0] = t[1]; bF[2 * np + 1][1] = t[3];
            }
#pragma unroll
            for (int mt = 0; mt < 4; mt++)
#pragma unroll
                for (int nt = 0; nt < 4; nt++)
                    mma_f16(acc[mt][nt], aF[mt], bF[nt]);
        }
        __syncthreads();
        if (++buf == 3) buf = 0;
    }
#undef LOAD_STAGE32

    if (mode == 0) {
#pragma unroll
        for (int mt = 0; mt < 4; mt++) {
#pragma unroll
            for (int nt = 0; nt < 4; nt++) {
                int col = bn + n0w + nt * 8 + (lane & 3) * 2;
                int s = col / 384;
                int rem = col - s * 384;
                int hh = rem >> 5, d = rem & 31;
                float sc = (s == 0) ? QSCL2E : 1.0f;
                float b0 = bias[col], b1 = bias[col + 1];
                char* plane = g_qkvp + ((s == 0) ? Q_OFF : (s == 1) ? K_OFF : V_OFF);
                int ch = d >> 3;
                int byt = (d & 7) * 2;
#pragma unroll
                for (int half2_ = 0; half2_ < 2; half2_++) {
                    int row = bm + m0w + mt * 16 + (lane >> 2) + half2_ * 8;
                    int b = row / 144, i = row - b * 144;
                    float v0 = (acc[mt][nt][half2_ * 2 + 0] + b0) * sc;
                    float v1 = (acc[mt][nt][half2_ * 2 + 1] + b1) * sc;
                    char* base = plane + ((size_t)(b * 12 + hh) * 144 + i) * 64;
                    *(uint32_t*)(base + ((ch ^ ((i >> 1) & 3)) * 16) + byt) =
                        packf2(v0, v1);
                }
            }
        }
    } else {
#pragma unroll
        for (int mt = 0; mt < 4; mt++) {
#pragma unroll
            for (int nt = 0; nt < 4; nt++) {
                int col = bn + n0w + nt * 8 + (lane & 3) * 2;
                float b0 = bias[col], b1 = bias[col + 1];
#pragma unroll
                for (int half2_ = 0; half2_ < 2; half2_++) {
                    int row = bm + m0w + mt * 16 + (lane >> 2) + half2_ * 8;
                    float2 v;
                    v.x = acc[mt][nt][half2_ * 2 + 0] + b0;
                    v.y = acc[mt][nt][half2_ * 2 + 1] + b1;
                    *(float2*)(outp + (size_t)row * 384 + col) = v;
                }
            }
        }
    }
}

// ---------------------------------------------------------------------------
// Flash-style HMMA attention, single fp16, base-2 softmax (no max pass).
// Q pre-scaled by QSCALE*log2e, mask pre-scaled (g_maskl), bias scaled at gather.
// ---------------------------------------------------------------------------
__global__ __launch_bounds__(288, 2)
void attn_mma_kernel(const float* __restrict__ bias_table,
                     const int*   __restrict__ pos_idx)
{
    extern __shared__ char sm[];
    char* sQ = sm;                     // 9216 B
    char* sK = sm + 9216;              // 9216 B
    char* sV = sm + 18432;             // 9216 B
    float* sB = (float*)(sm + 27648);  // 2592 floats
    const uint32_t uQ = smem_u32(sQ), uK = smem_u32(sK), uV = smem_u32(sV);

    const int bh = blockIdx.x;
    const int b = bh / HEADS, h = bh - b * HEADS;
    const int g  = b >> 5;
    const int t  = b & 31;
    const int mw = b & 7;

    const int tid = threadIdx.x;
    const int wid = tid >> 5, lane = tid & 31;

    // 1. QKV tile copy via cp.async
    {
        const char* q = g_qkvp + Q_OFF + (size_t)bh * 9216;
        const char* k = g_qkvp + K_OFF + (size_t)bh * 9216;
        const char* v = g_qkvp + V_OFF + (size_t)bh * 9216;
#pragma unroll
        for (int it = 0; it < 2; it++) {
            int i = tid + it * 288;
            cp_async16(uQ + i * 16, q + i * 16);
            cp_async16(uK + i * 16, k + i * 16);
            cp_async16(uV + i * 16, v + i * 16);
        }
        CP_COMMIT();
    }

    // 2. bias gather into registers (x log2e), latency overlapped with QK
    float bv[9];
#pragma unroll
    for (int kq = 0; kq < 9; kq++) {
        int s = tid + kq * 288;
        bv[kq] = bias_table[(size_t)pos_idx[8 * s + g] * (32 * HEADS) + t * HEADS + h]
                 * LOG2E;
    }

    CP_WAIT0();
    __syncthreads();

    const int m0 = wid * 16;
    const int gr = lane >> 2, q2 = lane & 3;
    const int i0 = m0 + gr, i1 = i0 + 8;

    // 3. QK^T (C zero-init; Q carries QSCALE*log2e)
    float c[18][4];
#pragma unroll
    for (int nt = 0; nt < 18; nt++)
#pragma unroll
        for (int e = 0; e < 4; e++) c[nt][e] = 0.f;

    const int lr = lane & 15, lc = lane >> 4;
#pragma unroll
    for (int kk = 0; kk < 2; kk++) {
        uint32_t aF[4];
        {
            int r = m0 + lr;
            int ch = kk * 2 + lc;
            ldsm_x4(aF, uQ + r * 64 + ((ch ^ ((r >> 1) & 3)) * 16));
        }
#pragma unroll
        for (int np = 0; np < 9; np++) {
            int r = np * 16 + lr;
            int ch = kk * 2 + lc;
            uint32_t tK[4];
            ldsm_x4(tK, uK + r * 64 + ((ch ^ ((r >> 1) & 3)) * 16));
            uint32_t b0[2] = {tK[0], tK[2]}, b1[2] = {tK[1], tK[3]};
            mma_f16(c[2 * np],     aF, b0);
            mma_f16(c[2 * np + 1], aF, b1);
        }
    }

    // 4. publish gathered bias
#pragma unroll
    for (int kq = 0; kq < 9; kq++) sB[tid + kq * 288] = bv[kq];
    __syncthreads();

    // 5. single-pass: e = 2^(c + mask + bias), accumulate sums (no max pass)
    float s0 = 0.f, s1 = 0.f;
    {
        const float* mrow0 = g_maskl + ((size_t)mw * 144 + i0) * 144;
        const float* mrow1 = g_maskl + ((size_t)mw * 144 + i1) * 144;
        const float* brow0 = sB + (i0 % 18) * 144;
        const float* brow1 = sB + (i1 % 18) * 144;
#pragma unroll
        for (int nt = 0; nt < 18; nt++) {
            int j = nt * 8 + q2 * 2;
            float2 mv0 = *(const float2*)(mrow0 + j);
            float2 mv1 = *(const float2*)(mrow1 + j);
            float2 bv0 = *(const float2*)(brow0 + j);
            float2 bv1 = *(const float2*)(brow1 + j);
            c[nt][0] = ex2(c[nt][0] + mv0.x + bv0.x); s0 += c[nt][0];
            c[nt][1] = ex2(c[nt][1] + mv0.y + bv0.y); s0 += c[nt][1];
            c[nt][2] = ex2(c[nt][2] + mv1.x + bv1.x); s1 += c[nt][2];
            c[nt][3] = ex2(c[nt][3] + mv1.y + bv1.y); s1 += c[nt][3];
        }
    }
    s0 += __shfl_xor_sync(0xffffffffu, s0, 1);
    s0 += __shfl_xor_sync(0xffffffffu, s0, 2);
    s1 += __shfl_xor_sync(0xffffffffu, s1, 1);
    s1 += __shfl_xor_sync(0xffffffffu, s1, 2);
    float inv0 = 1.f / s0, inv1 = 1.f / s1;

    // 6. pre-convert P to packed fp16 A-frags; c[] dies here
    uint32_t ph[36];
#pragma unroll
    for (int kk = 0; kk < 9; kk++) {
#pragma unroll
        for (int p = 0; p < 4; p++) {
            int nt = (p < 2) ? 2 * kk : 2 * kk + 1;
            float sc0 = (p & 1) ? inv1 : inv0;
            ph[kk * 4 + p] = packf2(c[nt][(p & 1) * 2 + 0] * sc0,
                                    c[nt][(p & 1) * 2 + 1] * sc0);
        }
    }

    // 7. PV
    float o[4][4];
#pragma unroll
    for (int ng = 0; ng < 4; ng++)
#pragma unroll
        for (int e = 0; e < 4; e++) o[ng][e] = 0.f;

    const int grp = lane >> 3, wi = lane & 7;
#pragma unroll
    for (int kk = 0; kk < 9; kk++) {
        int r = kk * 16 + (grp & 1) * 8 + wi;
#pragma unroll
        for (int ncp = 0; ncp < 2; ncp++) {
            int ch = ncp * 2 + (grp >> 1);
            uint32_t tv[4];
            ldsm_x4_t(tv, uV + r * 64 + ((ch ^ ((r >> 1) & 3)) * 16));
            uint32_t b0[2] = {tv[0], tv[1]}, b1[2] = {tv[2], tv[3]};
            mma_f16(o[ncp * 2],     ph + kk * 4, b0);
            mma_f16(o[ncp * 2 + 1], ph + kk * 4, b1);
        }
    }

    // 8. store fp16 att rows
#pragma unroll
    for (int ng = 0; ng < 4; ng++) {
        int d = ng * 8 + q2 * 2;
        int col = h * 32 + d;
        size_t r0o = ((size_t)b * 144 + i0) * 384 + col;
        size_t r1o = ((size_t)b * 144 + i1) * 384 + col;
        *(uint32_t*)(g_att + r0o) = packf2(o[ng][0], o[ng][1]);
        *(uint32_t*)(g_att + r1o) = packf2(o[ng][2], o[ng][3]);
    }
}

// ---------------------------------------------------------------------------
extern "C" void kernel_launch(void* const* d_in, const int* in_sizes, int n_in,
                              void* d_out, int out_size)
{
    const float* x          = (const float*)d_in[0];
    const float* mask       = (const float*)d_in[1];
    const float* w_qkv      = (const float*)d_in[2];
    const float* b_qkv      = (const float*)d_in[3];
    const float* w_out      = (const float*)d_in[4];
    const float* b_out      = (const float*)d_in[5];
    const float* bias_table = (const float*)d_in[6];
    const int*   pos_idx    = (const int*)d_in[7];
    float* out = (float*)d_out;

    __half *xa, *wqT, *woT, *att;
    float* maskl;
    cudaGetSymbolAddress((void**)&xa, g_xa);
    cudaGetSymbolAddress((void**)&wqT, g_wqkvT);
    cudaGetSymbolAddress((void**)&woT, g_woutT);
    cudaGetSymbolAddress((void**)&att, g_att);
    cudaGetSymbolAddress((void**)&maskl, g_maskl);

    const int smem_gemm = 3 * STG32;  // 48 KB
    cudaFuncSetAttribute(hmma_gemm_kernel, cudaFuncAttributeMaxDynamicSharedMemorySize,
                         smem_gemm);
    const int smem_attn = 3 * 9216 + 2592 * 4;  // 38016
    cudaFuncSetAttribute(attn_mma_kernel, cudaFuncAttributeMaxDynamicSharedMemorySize,
                         smem_attn);

    prep_kernel<<<1024, 256>>>(x, w_qkv, w_out, mask, xa, wqT, woT, maskl);
    // qkv projection -> packed q/k/v
    hmma_gemm_kernel<<<dim3(QKV_N / 128, MROWS / 128), 256, smem_gemm>>>(
        xa, wqT, b_qkv, nullptr, 0);
    // attention
    attn_mma_kernel<<<B_WIN * HEADS, 288, smem_attn>>>(bias_table, pos_idx);
    // output projection
    hmma_gemm_kernel<<<dim3(DIM / 128, MROWS / 128), 256, smem_gemm>>>(
        att, woT, b_out, out, 1);
}